// round 1
// baseline (speedup 1.0000x reference)
#include <cuda_runtime.h>
#include <math.h>

#define BATCH 4096

// ---------------- scratch (device globals; no allocation allowed) ----------
__device__ float g_h1[(long)BATCH * 8450];   // stage1 pooled features [B,50,13,13]
__device__ float g_h2[(long)BATCH * 1250];   // stage2 pooled features [B,50,5,5]
__device__ float g_f3[BATCH * 50];           // stage3 pooled features [B,50]
__device__ float g_t [BATCH * 500];          // shared 500-dim hidden (reused per stage)
__device__ float g_o1[BATCH * 10];
__device__ float g_o2[BATCH * 10];
__device__ float g_o3[BATCH * 10];
__device__ int   g_e1[BATCH];
__device__ int   g_e2[BATCH];

// ---------------- conv1: [B,1,28,28] -> relu+pool2 -> [B,50,13,13] ---------
__global__ void conv1_kernel(const float* __restrict__ x,
                             const float* __restrict__ w,   // [50,1,3,3]
                             const float* __restrict__ bias,
                             float* __restrict__ h1)
{
    int b = blockIdx.x;
    __shared__ float xs[28 * 28];
    __shared__ float ws[50 * 9];
    __shared__ float bs[50];
    const float* xb = x + (long)b * 784;
    for (int i = threadIdx.x; i < 784; i += blockDim.x) xs[i] = xb[i];
    for (int i = threadIdx.x; i < 450; i += blockDim.x) ws[i] = w[i];
    for (int i = threadIdx.x; i < 50;  i += blockDim.x) bs[i] = bias[i];
    __syncthreads();

    for (int idx = threadIdx.x; idx < 8450; idx += blockDim.x) {
        int oc = idx / 169;
        int p  = idx % 169;
        int py = p / 13, px = p % 13;
        const float* wk = ws + oc * 9;
        float m = -1e30f;
        #pragma unroll
        for (int dy = 0; dy < 2; dy++) {
            #pragma unroll
            for (int dx = 0; dx < 2; dx++) {
                int y = 2 * py + dy, xx = 2 * px + dx;
                float s = 0.f;
                #pragma unroll
                for (int ky = 0; ky < 3; ky++)
                    #pragma unroll
                    for (int kx = 0; kx < 3; kx++)
                        s += xs[(y + ky) * 28 + xx + kx] * wk[ky * 3 + kx];
                m = fmaxf(m, s);
            }
        }
        m += bs[oc];                  // bias after max (equal: max(a+c)=max(a)+c)
        h1[(long)b * 8450 + idx] = fmaxf(m, 0.f);
    }
}

// ---------------- conv2: [B,50,13,13] -> relu+pool2 -> [B,50,5,5] ----------
// per-sample block; h1 tile in SMEM; 10 output channels per thread (reg tile)
__global__ void conv2_kernel(const float* __restrict__ h1,
                             const float* __restrict__ w,   // [50,50,3,3]
                             const float* __restrict__ bias,
                             float* __restrict__ h2)
{
    int b = blockIdx.x;
    __shared__ float hs[8450];
    const float* hb = h1 + (long)b * 8450;
    for (int i = threadIdx.x; i < 8450; i += blockDim.x) hs[i] = hb[i];
    __syncthreads();

    int t = threadIdx.x;
    if (t >= 125) return;
    int pos = t / 5;            // 0..24
    int ocg = (t % 5) * 10;     // base output channel
    int py = pos / 5, px = pos % 5;
    int Y = 2 * py, X = 2 * px;

    float acc0[10], acc1[10], acc2[10], acc3[10];
    #pragma unroll
    for (int o = 0; o < 10; o++) { acc0[o]=0.f; acc1[o]=0.f; acc2[o]=0.f; acc3[o]=0.f; }

    for (int ic = 0; ic < 50; ic++) {
        const float* hc = hs + ic * 169;
        #pragma unroll
        for (int ky = 0; ky < 3; ky++) {
            #pragma unroll
            for (int kx = 0; kx < 3; kx++) {
                float h00 = hc[(Y + ky) * 13 + X + kx];
                float h01 = hc[(Y + ky) * 13 + X + 1 + kx];
                float h10 = hc[(Y + 1 + ky) * 13 + X + kx];
                float h11 = hc[(Y + 1 + ky) * 13 + X + 1 + kx];
                int widx = ic * 9 + ky * 3 + kx;
                #pragma unroll
                for (int o = 0; o < 10; o++) {
                    float wv = __ldg(&w[(ocg + o) * 450 + widx]);
                    acc0[o] += h00 * wv;
                    acc1[o] += h01 * wv;
                    acc2[o] += h10 * wv;
                    acc3[o] += h11 * wv;
                }
            }
        }
    }
    #pragma unroll
    for (int o = 0; o < 10; o++) {
        float m = fmaxf(fmaxf(acc0[o], acc1[o]), fmaxf(acc2[o], acc3[o]));
        m += __ldg(&bias[ocg + o]);
        h2[(long)b * 1250 + (ocg + o) * 25 + pos] = fmaxf(m, 0.f);
    }
}

// ---------------- conv3: [B,50,5,5] -> relu+pool2 -> [B,50] ----------------
__global__ void conv3_kernel(const float* __restrict__ h2,
                             const float* __restrict__ w,   // [50,50,3,3]
                             const float* __restrict__ bias,
                             float* __restrict__ f3)
{
    int b = blockIdx.x;
    __shared__ float hs[1250];
    const float* hb = h2 + (long)b * 1250;
    for (int i = threadIdx.x; i < 1250; i += blockDim.x) hs[i] = hb[i];
    __syncthreads();

    int oc = threadIdx.x;
    if (oc >= 50) return;
    float a0 = 0.f, a1 = 0.f, a2 = 0.f, a3 = 0.f;
    for (int ic = 0; ic < 50; ic++) {
        const float* hc = hs + ic * 25;
        #pragma unroll
        for (int ky = 0; ky < 3; ky++) {
            #pragma unroll
            for (int kx = 0; kx < 3; kx++) {
                float wv = __ldg(&w[oc * 450 + ic * 9 + ky * 3 + kx]);
                a0 += hc[ky * 5 + kx] * wv;
                a1 += hc[ky * 5 + kx + 1] * wv;
                a2 += hc[(ky + 1) * 5 + kx] * wv;
                a3 += hc[(ky + 1) * 5 + kx + 1] * wv;
            }
        }
    }
    float m = fmaxf(fmaxf(a0, a1), fmaxf(a2, a3)) + __ldg(&bias[oc]);
    f3[b * 50 + oc] = fmaxf(m, 0.f);
}

// ---------------- exit head: flag[b] = argmax( f[b] @ w^T + bias ) == 0 ----
__global__ void exit_kernel(const float* __restrict__ f, int K,
                            const float* __restrict__ w,    // [2,K]
                            const float* __restrict__ bias, // [2]
                            int* __restrict__ flag)
{
    int b = blockIdx.x;
    const float* fb = f + (long)b * K;
    float s0 = 0.f, s1 = 0.f;
    for (int k = threadIdx.x; k < K; k += blockDim.x) {
        float v = fb[k];
        s0 += v * __ldg(&w[k]);
        s1 += v * __ldg(&w[K + k]);
    }
    #pragma unroll
    for (int off = 16; off; off >>= 1) {
        s0 += __shfl_down_sync(0xffffffffu, s0, off);
        s1 += __shfl_down_sync(0xffffffffu, s1, off);
    }
    __shared__ float sh0[8], sh1[8];
    int wid = threadIdx.x >> 5, lane = threadIdx.x & 31;
    if (lane == 0) { sh0[wid] = s0; sh1[wid] = s1; }
    __syncthreads();
    if (threadIdx.x == 0) {
        float t0 = bias[0], t1 = bias[1];
        int nw = blockDim.x >> 5;
        for (int i = 0; i < nw; i++) { t0 += sh0[i]; t1 += sh1[i]; }
        flag[b] = (t0 >= t1) ? 1 : 0;   // argmax ties -> index 0
    }
}

// ---------------- tiled fp32 GEMM: C[m,n] = A[m,:] . W[n,:] + bias[n] ------
// A: [M,K] row-major; W: [N,K] row-major ("TN" layout, both K-contiguous)
#define GBM 128
#define GBN 64
#define GBK 16
#define GTM 8
#define GTN 4
__global__ __launch_bounds__(256)
void gemm_tn(const float* __restrict__ A, const float* __restrict__ W,
             const float* __restrict__ bias, float* __restrict__ C,
             int M, int N, int K, int relu)
{
    __shared__ float As[GBK][GBM + 4];
    __shared__ float Ws[GBK][GBN + 4];
    int tid = threadIdx.x;
    int bm = blockIdx.x * GBM;
    int bn = blockIdx.y * GBN;
    int tm = (tid / 16) * GTM;   // 0..120
    int tn = (tid % 16) * GTN;   // 0..60

    float acc[GTM][GTN];
    #pragma unroll
    for (int i = 0; i < GTM; i++)
        #pragma unroll
        for (int j = 0; j < GTN; j++) acc[i][j] = 0.f;

    for (int k0 = 0; k0 < K; k0 += GBK) {
        #pragma unroll
        for (int i = 0; i < (GBM * GBK) / 256; ++i) {     // 8 loads
            int idx = tid + i * 256;
            int row = idx / GBK, kk = idx % GBK;
            int gm = bm + row, gk = k0 + kk;
            As[kk][row] = (gk < K) ? A[(size_t)gm * K + gk] : 0.f;
        }
        #pragma unroll
        for (int i = 0; i < (GBN * GBK) / 256; ++i) {     // 4 loads
            int idx = tid + i * 256;
            int row = idx / GBK, kk = idx % GBK;
            int gn = bn + row, gk = k0 + kk;
            Ws[kk][row] = (gn < N && gk < K) ? W[(size_t)gn * K + gk] : 0.f;
        }
        __syncthreads();
        #pragma unroll
        for (int kk = 0; kk < GBK; ++kk) {
            float a[GTM], w[GTN];
            #pragma unroll
            for (int i = 0; i < GTM; i++) a[i] = As[kk][tm + i];
            #pragma unroll
            for (int j = 0; j < GTN; j++) w[j] = Ws[kk][tn + j];
            #pragma unroll
            for (int i = 0; i < GTM; i++)
                #pragma unroll
                for (int j = 0; j < GTN; j++) acc[i][j] += a[i] * w[j];
        }
        __syncthreads();
    }

    #pragma unroll
    for (int i = 0; i < GTM; i++) {
        int gm = bm + tm + i;
        #pragma unroll
        for (int j = 0; j < GTN; j++) {
            int gn = bn + tn + j;
            if (gn < N) {
                float v = acc[i][j] + __ldg(&bias[gn]);
                if (relu) v = fmaxf(v, 0.f);
                C[(size_t)gm * N + gn] = v;
            }
        }
    }
}

// ---------------- 10-way head: out[b,n] = t[b,:] . w[n,:] + bias[n] --------
__global__ void head_kernel(const float* __restrict__ t,
                            const float* __restrict__ w,    // [10,500]
                            const float* __restrict__ bias, // [10]
                            float* __restrict__ out)
{
    __shared__ float ws[10 * 500];
    __shared__ float bs[10];
    for (int i = threadIdx.x; i < 5000; i += blockDim.x) ws[i] = w[i];
    if (threadIdx.x < 10) bs[threadIdx.x] = bias[threadIdx.x];
    __syncthreads();
    int gid = blockIdx.x * blockDim.x + threadIdx.x;
    int b = gid / 10, n = gid % 10;
    if (b >= BATCH) return;
    const float* tb = t + (long)b * 500;
    const float* wn = ws + n * 500;
    float s = bs[n];
    #pragma unroll 4
    for (int k = 0; k < 500; k++) s += tb[k] * wn[k];
    out[b * 10 + n] = s;
}

// ---------------- select + log_softmax -------------------------------------
__global__ void final_kernel(const int* __restrict__ e1, const int* __restrict__ e2,
                             const float* __restrict__ o1, const float* __restrict__ o2,
                             const float* __restrict__ o3, float* __restrict__ out)
{
    int b = blockIdx.x * blockDim.x + threadIdx.x;
    if (b >= BATCH) return;
    const float* s = e1[b] ? (o1 + b * 10) : (e2[b] ? (o2 + b * 10) : (o3 + b * 10));
    float v[10], mx = -1e30f;
    #pragma unroll
    for (int i = 0; i < 10; i++) { v[i] = s[i]; mx = fmaxf(mx, v[i]); }
    float sum = 0.f;
    #pragma unroll
    for (int i = 0; i < 10; i++) sum += expf(v[i] - mx);
    float l = logf(sum);
    #pragma unroll
    for (int i = 0; i < 10; i++) out[b * 10 + i] = v[i] - mx - l;
}

// ---------------- launch ----------------------------------------------------
extern "C" void kernel_launch(void* const* d_in, const int* in_sizes, int n_in,
                              void* d_out, int out_size)
{
    const float* x      = (const float*)d_in[0];
    const float* c1_w   = (const float*)d_in[1];
    const float* c1_b   = (const float*)d_in[2];
    const float* c2_w   = (const float*)d_in[3];
    const float* c2_b   = (const float*)d_in[4];
    const float* c3_w   = (const float*)d_in[5];
    const float* c3_b   = (const float*)d_in[6];
    const float* l1c1_w = (const float*)d_in[7];
    const float* l1c1_b = (const float*)d_in[8];
    const float* l2c1_w = (const float*)d_in[9];
    const float* l2c1_b = (const float*)d_in[10];
    const float* l1c2_w = (const float*)d_in[11];
    const float* l1c2_b = (const float*)d_in[12];
    const float* l2c2_w = (const float*)d_in[13];
    const float* l2c2_b = (const float*)d_in[14];
    const float* l1_w   = (const float*)d_in[15];
    const float* l1_b   = (const float*)d_in[16];
    const float* l2_w   = (const float*)d_in[17];
    const float* l2_b   = (const float*)d_in[18];
    const float* d1_w   = (const float*)d_in[19];
    const float* d1_b   = (const float*)d_in[20];
    const float* d2_w   = (const float*)d_in[21];
    const float* d2_b   = (const float*)d_in[22];
    float* out = (float*)d_out;

    float *h1, *h2, *f3, *t, *o1, *o2, *o3;
    int *e1, *e2;
    cudaGetSymbolAddress((void**)&h1, g_h1);
    cudaGetSymbolAddress((void**)&h2, g_h2);
    cudaGetSymbolAddress((void**)&f3, g_f3);
    cudaGetSymbolAddress((void**)&t,  g_t);
    cudaGetSymbolAddress((void**)&o1, g_o1);
    cudaGetSymbolAddress((void**)&o2, g_o2);
    cudaGetSymbolAddress((void**)&o3, g_o3);
    cudaGetSymbolAddress((void**)&e1, g_e1);
    cudaGetSymbolAddress((void**)&e2, g_e2);

    // stage 1
    conv1_kernel<<<BATCH, 256>>>(x, c1_w, c1_b, h1);
    exit_kernel<<<BATCH, 256>>>(h1, 8450, d1_w, d1_b, e1);
    gemm_tn<<<dim3(BATCH / GBM, (500 + GBN - 1) / GBN), 256>>>(h1, l1c1_w, l1c1_b, t, BATCH, 500, 8450, 0);
    head_kernel<<<(BATCH * 10 + 255) / 256, 256>>>(t, l2c1_w, l2c1_b, o1);

    // stage 2
    conv2_kernel<<<BATCH, 128>>>(h1, c2_w, c2_b, h2);
    exit_kernel<<<BATCH, 256>>>(h2, 1250, d2_w, d2_b, e2);
    gemm_tn<<<dim3(BATCH / GBM, (500 + GBN - 1) / GBN), 256>>>(h2, l1c2_w, l1c2_b, t, BATCH, 500, 1250, 0);
    head_kernel<<<(BATCH * 10 + 255) / 256, 256>>>(t, l2c2_w, l2c2_b, o2);

    // stage 3
    conv3_kernel<<<BATCH, 64>>>(h2, c3_w, c3_b, f3);
    gemm_tn<<<dim3(BATCH / GBM, (500 + GBN - 1) / GBN), 256>>>(f3, l1_w, l1_b, t, BATCH, 500, 50, 1);
    head_kernel<<<(BATCH * 10 + 255) / 256, 256>>>(t, l2_w, l2_b, o3);

    // select + log_softmax
    final_kernel<<<(BATCH + 255) / 256, 256>>>(e1, e2, o1, o2, o3, out);
}

// round 3
// speedup vs baseline: 3.3488x; 3.3488x over previous
#include <cuda_runtime.h>
#include <cuda_bf16.h>
#include <math.h>
#include <stdint.h>

#define BATCH 4096
#define KP1 8512   // 8450 padded to mult of 32
#define KP2 1280   // 1250 padded to mult of 32

// ---------------- scratch (device globals; zero-initialized) ---------------
__device__ float g_h1[(size_t)BATCH * 8450];
__device__ float g_h2[(size_t)BATCH * 1250];
__device__ float g_f3[BATCH * 50];
__device__ float g_t [BATCH * 500];
__device__ float g_o1[BATCH * 10];
__device__ float g_o2[BATCH * 10];
__device__ float g_o3[BATCH * 10];
__device__ int   g_e1[BATCH];
__device__ int   g_e2[BATCH];
__device__ __nv_bfloat16 g_a1hi[(size_t)BATCH * KP1];
__device__ __nv_bfloat16 g_a1lo[(size_t)BATCH * KP1];
__device__ __nv_bfloat16 g_a2hi[(size_t)BATCH * KP2];
__device__ __nv_bfloat16 g_a2lo[(size_t)BATCH * KP2];
__device__ __nv_bfloat16 g_w1hi[(size_t)500 * KP1];
__device__ __nv_bfloat16 g_w1lo[(size_t)500 * KP1];
__device__ __nv_bfloat16 g_w2hi[(size_t)500 * KP2];
__device__ __nv_bfloat16 g_w2lo[(size_t)500 * KP2];

// ======================= warp-MMA helpers ===================================
__device__ __forceinline__ uint32_t smem_u32(const void* p) {
    uint32_t a;
    asm("{ .reg .u64 t; cvta.to.shared.u64 t, %1; cvt.u32.u64 %0, t; }"
        : "=r"(a) : "l"(p));
    return a;
}
__device__ __forceinline__ void ldsm_x4(uint32_t* r, uint32_t addr) {
    asm volatile("ldmatrix.sync.aligned.m8n8.x4.shared.b16 {%0,%1,%2,%3}, [%4];"
        : "=r"(r[0]), "=r"(r[1]), "=r"(r[2]), "=r"(r[3]) : "r"(addr));
}
__device__ __forceinline__ void ldsm_x2(uint32_t* r, uint32_t addr) {
    asm volatile("ldmatrix.sync.aligned.m8n8.x2.shared.b16 {%0,%1}, [%2];"
        : "=r"(r[0]), "=r"(r[1]) : "r"(addr));
}
__device__ __forceinline__ void mma16816(float* d, const uint32_t* a, const uint32_t* b) {
    asm volatile(
        "mma.sync.aligned.m16n8k16.row.col.f32.bf16.bf16.f32 "
        "{%0,%1,%2,%3}, {%4,%5,%6,%7}, {%8,%9}, {%0,%1,%2,%3};"
        : "+f"(d[0]), "+f"(d[1]), "+f"(d[2]), "+f"(d[3])
        : "r"(a[0]), "r"(a[1]), "r"(a[2]), "r"(a[3]), "r"(b[0]), "r"(b[1]));
}

// ============ bf16x3-split GEMM via mma.sync: C = A·W^T + bias ==============
// A(hi/lo): [M, Kp] bf16 K-major; W(hi/lo): [N, Kp] bf16 K-major; C: [M, N] f32
// block tile 128x64, K-chunk 32, 8 warps (4M x 2N), double-buffered smem.
#define GP 40                               // smem pitch (bf16 elems)
#define GEMM_BUF_ELEMS (384 * GP)           // Ah+Al (128 rows) + Wh+Wl (64 rows)
#define GEMM_SMEM_BYTES (2 * GEMM_BUF_ELEMS * 2)

__global__ __launch_bounds__(256, 1) void gemm_mma(
    const __nv_bfloat16* __restrict__ Ahi, const __nv_bfloat16* __restrict__ Alo,
    const __nv_bfloat16* __restrict__ Whi, const __nv_bfloat16* __restrict__ Wlo,
    const float* __restrict__ bias, float* __restrict__ C,
    int N, int Kp, int relu)
{
    extern __shared__ __nv_bfloat16 sm[];
    const int tid  = threadIdx.x;
    const int lane = tid & 31;
    const int wid  = tid >> 5;
    const int wm   = (wid & 3) * 32;        // warp M offset in tile
    const int wn   = (wid >> 2) * 32;       // warp N offset in tile
    const int bm   = blockIdx.x * 128;
    const int bn   = blockIdx.y * 64;
    const int nc   = Kp >> 5;               // #K-chunks of 32

    // per-buffer element offsets
    const int OAh = 0, OAl = 128 * GP, OWh = 256 * GP, OWl = 320 * GP;

    float acc[2][4][4];
    #pragma unroll
    for (int i = 0; i < 2; i++)
        #pragma unroll
        for (int j = 0; j < 4; j++)
            #pragma unroll
            for (int k = 0; k < 4; k++) acc[i][j][k] = 0.f;

    auto load_chunk = [&](int c, int b) {
        __nv_bfloat16* dst = sm + b * GEMM_BUF_ELEMS;
        const size_t kof = (size_t)c * 32;
        // A: 128 rows x 32 cols, hi+lo : 2 uint4 per thread per array
        #pragma unroll
        for (int i = 0; i < 2; i++) {
            int idx = tid + i * 256;
            int row = idx >> 2, q = idx & 3;
            const size_t so = (size_t)(bm + row) * Kp + kof + q * 8;
            *(uint4*)(dst + OAh + row * GP + q * 8) = *(const uint4*)(Ahi + so);
            *(uint4*)(dst + OAl + row * GP + q * 8) = *(const uint4*)(Alo + so);
        }
        // W: 64 rows x 32 cols, hi+lo : 1 uint4 per thread per array (guard N)
        {
            int row = tid >> 2, q = tid & 3;
            uint4 vh = make_uint4(0, 0, 0, 0), vl = vh;
            if (bn + row < N) {
                const size_t so = (size_t)(bn + row) * Kp + kof + q * 8;
                vh = *(const uint4*)(Whi + so);
                vl = *(const uint4*)(Wlo + so);
            }
            *(uint4*)(dst + OWh + row * GP + q * 8) = vh;
            *(uint4*)(dst + OWl + row * GP + q * 8) = vl;
        }
    };

    auto compute_chunk = [&](int b) {
        const uint32_t base = smem_u32(sm + b * GEMM_BUF_ELEMS);
        #pragma unroll
        for (int ks = 0; ks < 2; ks++) {
            uint32_t ah[2][4], al[2][4], wh[4][2], wl[4][2];
            #pragma unroll
            for (int mf = 0; mf < 2; mf++) {
                int row = wm + mf * 16 + (lane & 15);
                int col = ks * 16 + ((lane >> 4) << 3);
                uint32_t ad = base + (uint32_t)(row * GP + col) * 2;
                ldsm_x4(ah[mf], ad);
                ldsm_x4(al[mf], ad + OAl * 2);
            }
            #pragma unroll
            for (int nf = 0; nf < 4; nf++) {
                int row = wn + nf * 8 + (lane & 7);
                int col = ks * 16 + (((lane >> 3) & 1) << 3);
                uint32_t wd = base + (uint32_t)(OWh * 2) + (uint32_t)(row * GP + col) * 2;
                ldsm_x2(wh[nf], wd);
                ldsm_x2(wl[nf], wd + (OWl - OWh) * 2);
            }
            #pragma unroll
            for (int mf = 0; mf < 2; mf++)
                #pragma unroll
                for (int nf = 0; nf < 4; nf++) {
                    mma16816(acc[mf][nf], ah[mf], wh[nf]);
                    mma16816(acc[mf][nf], ah[mf], wl[nf]);
                    mma16816(acc[mf][nf], al[mf], wh[nf]);
                }
        }
    };

    load_chunk(0, 0);
    __syncthreads();
    for (int c = 0; c < nc; c++) {
        const int b = c & 1;
        if (c + 1 < nc) load_chunk(c + 1, b ^ 1);
        compute_chunk(b);
        __syncthreads();
    }

    // epilogue
    #pragma unroll
    for (int mf = 0; mf < 2; mf++)
        #pragma unroll
        for (int nf = 0; nf < 4; nf++) {
            float* a = acc[mf][nf];
            int r0 = bm + wm + mf * 16 + (lane >> 2);
            int cn = bn + wn + nf * 8 + (lane & 3) * 2;
            if (cn < N) {
                float b0 = __ldg(&bias[cn]), b1 = __ldg(&bias[cn + 1]);
                float v00 = a[0] + b0, v01 = a[1] + b1;
                float v10 = a[2] + b0, v11 = a[3] + b1;
                if (relu) {
                    v00 = fmaxf(v00, 0.f); v01 = fmaxf(v01, 0.f);
                    v10 = fmaxf(v10, 0.f); v11 = fmaxf(v11, 0.f);
                }
                C[(size_t)r0 * N + cn]           = v00;
                C[(size_t)r0 * N + cn + 1]       = v01;
                C[(size_t)(r0 + 8) * N + cn]     = v10;
                C[(size_t)(r0 + 8) * N + cn + 1] = v11;
            }
        }
}

// --------- weight split conversion: fp32 [N,K] -> bf16 hi/lo [N,Kp] --------
__global__ void convert_w(const float* __restrict__ w,
                          __nv_bfloat16* __restrict__ hi,
                          __nv_bfloat16* __restrict__ lo,
                          int NK, int K, int Kp)
{
    int i = blockIdx.x * blockDim.x + threadIdx.x;
    if (i >= NK) return;
    int n = i / K, k = i - n * K;
    float v = w[i];
    __nv_bfloat16 h = __float2bfloat16(v);
    hi[(size_t)n * Kp + k] = h;
    lo[(size_t)n * Kp + k] = __float2bfloat16(v - __bfloat162float(h));
}

// ---------------- conv1: [B,1,28,28] -> relu+pool2 -> [B,50,13,13] ---------
__global__ void conv1_kernel(const float* __restrict__ x,
                             const float* __restrict__ w,
                             const float* __restrict__ bias,
                             float* __restrict__ h1,
                             __nv_bfloat16* __restrict__ ahi,
                             __nv_bfloat16* __restrict__ alo)
{
    int b = blockIdx.x;
    __shared__ float xs[28 * 28];
    __shared__ float ws[50 * 9];
    __shared__ float bs[50];
    const float* xb = x + (size_t)b * 784;
    for (int i = threadIdx.x; i < 784; i += blockDim.x) xs[i] = xb[i];
    for (int i = threadIdx.x; i < 450; i += blockDim.x) ws[i] = w[i];
    for (int i = threadIdx.x; i < 50;  i += blockDim.x) bs[i] = bias[i];
    __syncthreads();

    for (int idx = threadIdx.x; idx < 8450; idx += blockDim.x) {
        int oc = idx / 169;
        int p  = idx % 169;
        int py = p / 13, px = p % 13;
        const float* wk = ws + oc * 9;
        float m = -1e30f;
        #pragma unroll
        for (int dy = 0; dy < 2; dy++)
            #pragma unroll
            for (int dx = 0; dx < 2; dx++) {
                int y = 2 * py + dy, xx = 2 * px + dx;
                float s = 0.f;
                #pragma unroll
                for (int ky = 0; ky < 3; ky++)
                    #pragma unroll
                    for (int kx = 0; kx < 3; kx++)
                        s += xs[(y + ky) * 28 + xx + kx] * wk[ky * 3 + kx];
                m = fmaxf(m, s);
            }
        m += bs[oc];
        float v = fmaxf(m, 0.f);
        h1[(size_t)b * 8450 + idx] = v;
        __nv_bfloat16 h = __float2bfloat16(v);
        ahi[(size_t)b * KP1 + idx] = h;
        alo[(size_t)b * KP1 + idx] = __float2bfloat16(v - __bfloat162float(h));
    }
}

// ---------------- conv2 (skips exited samples) ------------------------------
__global__ void conv2_kernel(const float* __restrict__ h1,
                             const float* __restrict__ w,
                             const float* __restrict__ bias,
                             float* __restrict__ h2,
                             __nv_bfloat16* __restrict__ ahi,
                             __nv_bfloat16* __restrict__ alo,
                             const int* __restrict__ e1)
{
    int b = blockIdx.x;
    if (e1[b]) return;   // h2/a2 rows stay zero; out2 never selected for b
    __shared__ float hs[8450];
    const float* hb = h1 + (size_t)b * 8450;
    for (int i = threadIdx.x; i < 8450; i += blockDim.x) hs[i] = hb[i];
    __syncthreads();

    int t = threadIdx.x;
    if (t >= 125) return;
    int pos = t / 5;
    int ocg = (t % 5) * 10;
    int py = pos / 5, px = pos % 5;
    int Y = 2 * py, X = 2 * px;

    float acc0[10], acc1[10], acc2[10], acc3[10];
    #pragma unroll
    for (int o = 0; o < 10; o++) { acc0[o]=0.f; acc1[o]=0.f; acc2[o]=0.f; acc3[o]=0.f; }

    for (int ic = 0; ic < 50; ic++) {
        const float* hc = hs + ic * 169;
        #pragma unroll
        for (int ky = 0; ky < 3; ky++)
            #pragma unroll
            for (int kx = 0; kx < 3; kx++) {
                float h00 = hc[(Y + ky) * 13 + X + kx];
                float h01 = hc[(Y + ky) * 13 + X + 1 + kx];
                float h10 = hc[(Y + 1 + ky) * 13 + X + kx];
                float h11 = hc[(Y + 1 + ky) * 13 + X + 1 + kx];
                int widx = ic * 9 + ky * 3 + kx;
                #pragma unroll
                for (int o = 0; o < 10; o++) {
                    float wv = __ldg(&w[(ocg + o) * 450 + widx]);
                    acc0[o] += h00 * wv;
                    acc1[o] += h01 * wv;
                    acc2[o] += h10 * wv;
                    acc3[o] += h11 * wv;
                }
            }
    }
    #pragma unroll
    for (int o = 0; o < 10; o++) {
        float m = fmaxf(fmaxf(acc0[o], acc1[o]), fmaxf(acc2[o], acc3[o]));
        m += __ldg(&bias[ocg + o]);
        float v = fmaxf(m, 0.f);
        int idx = (ocg + o) * 25 + pos;
        h2[(size_t)b * 1250 + idx] = v;
        __nv_bfloat16 h = __float2bfloat16(v);
        ahi[(size_t)b * KP2 + idx] = h;
        alo[(size_t)b * KP2 + idx] = __float2bfloat16(v - __bfloat162float(h));
    }
}

// ---------------- conv3 (skips samples exiting at 1 or 2) -------------------
__global__ void conv3_kernel(const float* __restrict__ h2,
                             const float* __restrict__ w,
                             const float* __restrict__ bias,
                             float* __restrict__ f3,
                             const int* __restrict__ e1,
                             const int* __restrict__ e2)
{
    int b = blockIdx.x;
    if (e1[b] || e2[b]) return;
    __shared__ float hs[1250];
    const float* hb = h2 + (size_t)b * 1250;
    for (int i = threadIdx.x; i < 1250; i += blockDim.x) hs[i] = hb[i];
    __syncthreads();

    int oc = threadIdx.x;
    if (oc >= 50) return;
    float a0 = 0.f, a1 = 0.f, a2 = 0.f, a3 = 0.f;
    for (int ic = 0; ic < 50; ic++) {
        const float* hc = hs + ic * 25;
        #pragma unroll
        for (int ky = 0; ky < 3; ky++)
            #pragma unroll
            for (int kx = 0; kx < 3; kx++) {
                float wv = __ldg(&w[oc * 450 + ic * 9 + ky * 3 + kx]);
                a0 += hc[ky * 5 + kx] * wv;
                a1 += hc[ky * 5 + kx + 1] * wv;
                a2 += hc[(ky + 1) * 5 + kx] * wv;
                a3 += hc[(ky + 1) * 5 + kx + 1] * wv;
            }
    }
    float m = fmaxf(fmaxf(a0, a1), fmaxf(a2, a3)) + __ldg(&bias[oc]);
    f3[b * 50 + oc] = fmaxf(m, 0.f);
}

// ---------------- exit head -------------------------------------------------
__global__ void exit_kernel(const float* __restrict__ f, int K,
                            const float* __restrict__ w,
                            const float* __restrict__ bias,
                            int* __restrict__ flag,
                            const int* __restrict__ skip)
{
    int b = blockIdx.x;
    if (skip && skip[b]) { if (threadIdx.x == 0) flag[b] = 0; return; }
    const float* fb = f + (size_t)b * K;
    float s0 = 0.f, s1 = 0.f;
    for (int k = threadIdx.x; k < K; k += blockDim.x) {
        float v = fb[k];
        s0 += v * __ldg(&w[k]);
        s1 += v * __ldg(&w[K + k]);
    }
    #pragma unroll
    for (int off = 16; off; off >>= 1) {
        s0 += __shfl_down_sync(0xffffffffu, s0, off);
        s1 += __shfl_down_sync(0xffffffffu, s1, off);
    }
    __shared__ float sh0[8], sh1[8];
    int wid = threadIdx.x >> 5, lane = threadIdx.x & 31;
    if (lane == 0) { sh0[wid] = s0; sh1[wid] = s1; }
    __syncthreads();
    if (threadIdx.x == 0) {
        float t0 = bias[0], t1 = bias[1];
        int nw = blockDim.x >> 5;
        for (int i = 0; i < nw; i++) { t0 += sh0[i]; t1 += sh1[i]; }
        flag[b] = (t0 >= t1) ? 1 : 0;
    }
}

// ---------------- SIMT GEMM (stage-3 l1, K=50 tiny) -------------------------
#define GBM 128
#define GBN 64
#define GBK 16
#define GTM 8
#define GTN 4
__global__ __launch_bounds__(256)
void gemm_tn(const float* __restrict__ A, const float* __restrict__ W,
             const float* __restrict__ bias, float* __restrict__ C,
             int M, int N, int K, int relu)
{
    __shared__ float As[GBK][GBM + 4];
    __shared__ float Ws[GBK][GBN + 4];
    int tid = threadIdx.x;
    int bm = blockIdx.x * GBM;
    int bn = blockIdx.y * GBN;
    int tm = (tid / 16) * GTM;
    int tn = (tid % 16) * GTN;

    float acc[GTM][GTN];
    #pragma unroll
    for (int i = 0; i < GTM; i++)
        #pragma unroll
        for (int j = 0; j < GTN; j++) acc[i][j] = 0.f;

    for (int k0 = 0; k0 < K; k0 += GBK) {
        #pragma unroll
        for (int i = 0; i < (GBM * GBK) / 256; ++i) {
            int idx = tid + i * 256;
            int row = idx / GBK, kk = idx % GBK;
            int gm = bm + row, gk = k0 + kk;
            As[kk][row] = (gk < K) ? A[(size_t)gm * K + gk] : 0.f;
        }
        #pragma unroll
        for (int i = 0; i < (GBN * GBK) / 256; ++i) {
            int idx = tid + i * 256;
            int row = idx / GBK, kk = idx % GBK;
            int gn = bn + row, gk = k0 + kk;
            Ws[kk][row] = (gn < N && gk < K) ? W[(size_t)gn * K + gk] : 0.f;
        }
        __syncthreads();
        #pragma unroll
        for (int kk = 0; kk < GBK; ++kk) {
            float a[GTM], w[GTN];
            #pragma unroll
            for (int i = 0; i < GTM; i++) a[i] = As[kk][tm + i];
            #pragma unroll
            for (int j = 0; j < GTN; j++) w[j] = Ws[kk][tn + j];
            #pragma unroll
            for (int i = 0; i < GTM; i++)
                #pragma unroll
                for (int j = 0; j < GTN; j++) acc[i][j] += a[i] * w[j];
        }
        __syncthreads();
    }

    #pragma unroll
    for (int i = 0; i < GTM; i++) {
        int gm = bm + tm + i;
        #pragma unroll
        for (int j = 0; j < GTN; j++) {
            int gn = bn + tn + j;
            if (gn < N) {
                float v = acc[i][j] + __ldg(&bias[gn]);
                if (relu) v = fmaxf(v, 0.f);
                C[(size_t)gm * N + gn] = v;
            }
        }
    }
}

// ---------------- 10-way head: warp per sample ------------------------------
__global__ __launch_bounds__(256)
void head_kernel(const float* __restrict__ t,
                 const float* __restrict__ w,
                 const float* __restrict__ bias,
                 float* __restrict__ out)
{
    __shared__ float ws[5000];
    for (int i = threadIdx.x; i < 5000; i += 256) ws[i] = w[i];
    __syncthreads();
    int wid = threadIdx.x >> 5, lane = threadIdx.x & 31;
    int b = blockIdx.x * 8 + wid;
    const float* tb = t + (size_t)b * 500;
    float acc[10];
    #pragma unroll
    for (int n = 0; n < 10; n++) acc[n] = 0.f;
    for (int k = lane; k < 500; k += 32) {
        float tv = tb[k];
        #pragma unroll
        for (int n = 0; n < 10; n++) acc[n] += tv * ws[n * 500 + k];
    }
    #pragma unroll
    for (int n = 0; n < 10; n++)
        #pragma unroll
        for (int off = 16; off; off >>= 1)
            acc[n] += __shfl_xor_sync(0xffffffffu, acc[n], off);
    if (lane == 0) {
        #pragma unroll
        for (int n = 0; n < 10; n++) out[b * 10 + n] = acc[n] + __ldg(&bias[n]);
    }
}

// ---------------- select + log_softmax -------------------------------------
__global__ void final_kernel(const int* __restrict__ e1, const int* __restrict__ e2,
                             const float* __restrict__ o1, const float* __restrict__ o2,
                             const float* __restrict__ o3, float* __restrict__ out)
{
    int b = blockIdx.x * blockDim.x + threadIdx.x;
    if (b >= BATCH) return;
    const float* s = e1[b] ? (o1 + b * 10) : (e2[b] ? (o2 + b * 10) : (o3 + b * 10));
    float v[10], mx = -1e30f;
    #pragma unroll
    for (int i = 0; i < 10; i++) { v[i] = s[i]; mx = fmaxf(mx, v[i]); }
    float sum = 0.f;
    #pragma unroll
    for (int i = 0; i < 10; i++) sum += expf(v[i] - mx);
    float l = logf(sum);
    #pragma unroll
    for (int i = 0; i < 10; i++) out[b * 10 + i] = v[i] - mx - l;
}

// ---------------- launch ----------------------------------------------------
extern "C" void kernel_launch(void* const* d_in, const int* in_sizes, int n_in,
                              void* d_out, int out_size)
{
    const float* x      = (const float*)d_in[0];
    const float* c1_w   = (const float*)d_in[1];
    const float* c1_b   = (const float*)d_in[2];
    const float* c2_w   = (const float*)d_in[3];
    const float* c2_b   = (const float*)d_in[4];
    const float* c3_w   = (const float*)d_in[5];
    const float* c3_b   = (const float*)d_in[6];
    const float* l1c1_w = (const float*)d_in[7];
    const float* l1c1_b = (const float*)d_in[8];
    const float* l2c1_w = (const float*)d_in[9];
    const float* l2c1_b = (const float*)d_in[10];
    const float* l1c2_w = (const float*)d_in[11];
    const float* l1c2_b = (const float*)d_in[12];
    const float* l2c2_w = (const float*)d_in[13];
    const float* l2c2_b = (const float*)d_in[14];
    const float* l1_w   = (const float*)d_in[15];
    const float* l1_b   = (const float*)d_in[16];
    const float* l2_w   = (const float*)d_in[17];
    const float* l2_b   = (const float*)d_in[18];
    const float* d1_w   = (const float*)d_in[19];
    const float* d1_b   = (const float*)d_in[20];
    const float* d2_w   = (const float*)d_in[21];
    const float* d2_b   = (const float*)d_in[22];
    float* out = (float*)d_out;

    float *h1, *h2, *f3, *t, *o1, *o2, *o3;
    int *e1, *e2;
    __nv_bfloat16 *a1hi, *a1lo, *a2hi, *a2lo, *w1hi, *w1lo, *w2hi, *w2lo;
    cudaGetSymbolAddress((void**)&h1, g_h1);
    cudaGetSymbolAddress((void**)&h2, g_h2);
    cudaGetSymbolAddress((void**)&f3, g_f3);
    cudaGetSymbolAddress((void**)&t,  g_t);
    cudaGetSymbolAddress((void**)&o1, g_o1);
    cudaGetSymbolAddress((void**)&o2, g_o2);
    cudaGetSymbolAddress((void**)&o3, g_o3);
    cudaGetSymbolAddress((void**)&e1, g_e1);
    cudaGetSymbolAddress((void**)&e2, g_e2);
    cudaGetSymbolAddress((void**)&a1hi, g_a1hi);
    cudaGetSymbolAddress((void**)&a1lo, g_a1lo);
    cudaGetSymbolAddress((void**)&a2hi, g_a2hi);
    cudaGetSymbolAddress((void**)&a2lo, g_a2lo);
    cudaGetSymbolAddress((void**)&w1hi, g_w1hi);
    cudaGetSymbolAddress((void**)&w1lo, g_w1lo);
    cudaGetSymbolAddress((void**)&w2hi, g_w2hi);
    cudaGetSymbolAddress((void**)&w2lo, g_w2lo);

    static int smem_set = 0;
    if (!smem_set) {
        cudaFuncSetAttribute(gemm_mma, cudaFuncAttributeMaxDynamicSharedMemorySize,
                             GEMM_SMEM_BYTES);
        smem_set = 1;
    }

    // weight splits
    convert_w<<<(500 * 8450 + 255) / 256, 256>>>(l1c1_w, w1hi, w1lo, 500 * 8450, 8450, KP1);
    convert_w<<<(500 * 1250 + 255) / 256, 256>>>(l1c2_w, w2hi, w2lo, 500 * 1250, 1250, KP2);

    // stage 1
    conv1_kernel<<<BATCH, 256>>>(x, c1_w, c1_b, h1, a1hi, a1lo);
    exit_kernel<<<BATCH, 256>>>(h1, 8450, d1_w, d1_b, e1, nullptr);
    gemm_mma<<<dim3(BATCH / 128, 8), 256, GEMM_SMEM_BYTES>>>(
        a1hi, a1lo, w1hi, w1lo, l1c1_b, t, 500, KP1, 0);
    head_kernel<<<BATCH / 8, 256>>>(t, l2c1_w, l2c1_b, o1);

    // stage 2
    conv2_kernel<<<BATCH, 128>>>(h1, c2_w, c2_b, h2, a2hi, a2lo, e1);
    exit_kernel<<<BATCH, 256>>>(h2, 1250, d2_w, d2_b, e2, e1);
    gemm_mma<<<dim3(BATCH / 128, 8), 256, GEMM_SMEM_BYTES>>>(
        a2hi, a2lo, w2hi, w2lo, l1c2_b, t, 500, KP2, 0);
    head_kernel<<<BATCH / 8, 256>>>(t, l2c2_w, l2c2_b, o2);

    // stage 3
    conv3_kernel<<<BATCH, 64>>>(h2, c3_w, c3_b, f3, e1, e2);
    gemm_tn<<<dim3(BATCH / GBM, 8), 256>>>(f3, l1_w, l1_b, t, BATCH, 500, 50, 1);
    head_kernel<<<BATCH / 8, 256>>>(t, l2_w, l2_b, o3);

    final_kernel<<<(BATCH + 255) / 256, 256>>>(e1, e2, o1, o2, o3, out);
}

// round 4
// speedup vs baseline: 3.4827x; 1.0400x over previous
#include <cuda_runtime.h>
#include <math.h>
#include <stdint.h>

#define BATCH 4096
#define K1 8450
#define K2 1250

// ---------------- scratch (device globals; zero-initialized) ---------------
// +1024 pad so chunked float2 loads past row-end stay in-bounds
__device__ float g_h1[(size_t)BATCH * K1 + 1024];
__device__ float g_h2[(size_t)BATCH * K2 + 1024];
__device__ float g_f3[BATCH * 50];
__device__ float g_o1[BATCH * 10];
__device__ float g_o2[BATCH * 10];
__device__ float g_o3[BATCH * 10];
__device__ int   g_e1[BATCH];
__device__ int   g_e2[BATCH];
__device__ float g_wc1[10 * K1];
__device__ float g_bc1[10];
__device__ float g_wc2[10 * K2];
__device__ float g_bc2[10];

// ========== combine: Wc[10,K] = l2[10,500] @ l1[500,K]; bc = l2@b1 + b2 =====
__global__ __launch_bounds__(256) void combine_kernel(
    const float* __restrict__ l1, const float* __restrict__ b1,
    const float* __restrict__ l2, const float* __restrict__ b2,
    int K, float* __restrict__ Wc, float* __restrict__ bc)
{
    __shared__ float l2T[500 * 12];     // transposed, padded to 12 for vec loads
    int tid = threadIdx.x;
    for (int i = tid; i < 5000; i += 256) {
        int j = i / 500, r = i - j * 500;
        l2T[r * 12 + j] = l2[i];
    }
    for (int i = tid + 5000; i < 6000; i += 256) {   // zero pad cols 10,11
        int r = (i - 5000); if (r < 500) { l2T[r * 12 + 10] = 0.f; l2T[r * 12 + 11] = 0.f; }
    }
    __syncthreads();

    int k = blockIdx.x * 256 + tid;
    if (k < K) {
        float acc[10];
        #pragma unroll
        for (int j = 0; j < 10; j++) acc[j] = 0.f;
        for (int r = 0; r < 500; r++) {
            float a = __ldg(&l1[(size_t)r * K + k]);
            float4 w0 = *(const float4*)&l2T[r * 12];
            float4 w1 = *(const float4*)&l2T[r * 12 + 4];
            float2 w2 = *(const float2*)&l2T[r * 12 + 8];
            acc[0] += a * w0.x; acc[1] += a * w0.y; acc[2] += a * w0.z; acc[3] += a * w0.w;
            acc[4] += a * w1.x; acc[5] += a * w1.y; acc[6] += a * w1.z; acc[7] += a * w1.w;
            acc[8] += a * w2.x; acc[9] += a * w2.y;
        }
        #pragma unroll
        for (int j = 0; j < 10; j++) Wc[(size_t)j * K + k] = acc[j];
    }
    if (blockIdx.x == 0 && tid < 10) {
        float a = b2[tid];
        for (int r = 0; r < 500; r++) a += l2[tid * 500 + r] * b1[r];
        bc[tid] = a;
    }
}

// ---------------- conv1: [B,1,28,28] -> relu+pool2 -> [B,50,13,13] ---------
__global__ void conv1_kernel(const float* __restrict__ x,
                             const float* __restrict__ w,
                             const float* __restrict__ bias,
                             float* __restrict__ h1)
{
    int b = blockIdx.x;
    __shared__ float xs[28 * 28];
    __shared__ float ws[50 * 9];
    __shared__ float bs[50];
    const float* xb = x + (size_t)b * 784;
    for (int i = threadIdx.x; i < 784; i += blockDim.x) xs[i] = xb[i];
    for (int i = threadIdx.x; i < 450; i += blockDim.x) ws[i] = w[i];
    for (int i = threadIdx.x; i < 50;  i += blockDim.x) bs[i] = bias[i];
    __syncthreads();

    for (int idx = threadIdx.x; idx < 8450; idx += blockDim.x) {
        int oc = idx / 169;
        int p  = idx % 169;
        int py = p / 13, px = p % 13;
        const float* wk = ws + oc * 9;
        float m = -1e30f;
        #pragma unroll
        for (int dy = 0; dy < 2; dy++)
            #pragma unroll
            for (int dx = 0; dx < 2; dx++) {
                int y = 2 * py + dy, xx = 2 * px + dx;
                float s = 0.f;
                #pragma unroll
                for (int ky = 0; ky < 3; ky++)
                    #pragma unroll
                    for (int kx = 0; kx < 3; kx++)
                        s += xs[(y + ky) * 28 + xx + kx] * wk[ky * 3 + kx];
                m = fmaxf(m, s);
            }
        m += bs[oc];
        h1[(size_t)b * K1 + idx] = fmaxf(m, 0.f);
    }
}

// ====== stagehead: per-sample 12 dots over K (10 combined out + 2 exit) =====
// block = 32 samples; weights + feature tile staged in smem; warp = 4 samples.
#define SH_G 32
#define SH_CK 1024
#define SH_SMEM ((12 * SH_CK + SH_G * SH_CK) * 4)   // 48 KB + 128 KB

__global__ __launch_bounds__(256) void stagehead_kernel(
    const float* __restrict__ f, int K,
    const float* __restrict__ Wc, const float* __restrict__ bc,
    const float* __restrict__ dw, const float* __restrict__ db,
    float* __restrict__ o, int* __restrict__ e)
{
    extern __shared__ float sh[];
    float* ws = sh;                 // [12][SH_CK]
    float* hs = sh + 12 * SH_CK;    // [SH_G][SH_CK]
    const int tid = threadIdx.x, lane = tid & 31, wid = tid >> 5;
    const int b0 = blockIdx.x * SH_G;

    float acc[4][12];
    #pragma unroll
    for (int s = 0; s < 4; s++)
        #pragma unroll
        for (int j = 0; j < 12; j++) acc[s][j] = 0.f;

    const int nchunks = (K + SH_CK - 1) / SH_CK;
    for (int c = 0; c < nchunks; c++) {
        const int kc = c * SH_CK;
        // stage weights (zero-filled past K)
        for (int i = tid; i < 12 * SH_CK; i += 256) {
            int j = i >> 10, kk = i & (SH_CK - 1);
            int k = kc + kk;
            float v = 0.f;
            if (k < K) v = (j < 10) ? Wc[(size_t)j * K + k] : dw[(size_t)(j - 10) * K + k];
            ws[i] = v;
        }
        // stage feature tile (float2; rows are even-length, array padded)
        for (int i = tid; i < SH_G * (SH_CK / 2); i += 256) {
            int s = i / (SH_CK / 2), kk2 = i - s * (SH_CK / 2);
            float2 v = *(const float2*)(f + (size_t)(b0 + s) * K + kc + kk2 * 2);
            *(float2*)(hs + s * SH_CK + kk2 * 2) = v;
        }
        __syncthreads();

        const int sbase = wid * 4;
        for (int kk = 0; kk < SH_CK; kk += 32) {
            const int ki = kk + lane;
            float wr[12];
            #pragma unroll
            for (int j = 0; j < 12; j++) wr[j] = ws[j * SH_CK + ki];
            #pragma unroll
            for (int s = 0; s < 4; s++) {
                float v = hs[(sbase + s) * SH_CK + ki];
                #pragma unroll
                for (int j = 0; j < 12; j++) acc[s][j] += v * wr[j];
            }
        }
        __syncthreads();
    }

    #pragma unroll
    for (int s = 0; s < 4; s++) {
        #pragma unroll
        for (int j = 0; j < 12; j++) {
            #pragma unroll
            for (int off = 16; off; off >>= 1)
                acc[s][j] += __shfl_xor_sync(0xffffffffu, acc[s][j], off);
        }
        if (lane == 0) {
            int b = b0 + wid * 4 + s;
            #pragma unroll
            for (int j = 0; j < 10; j++) o[b * 10 + j] = acc[s][j] + bc[j];
            float m0 = acc[s][10] + db[0];
            float m1 = acc[s][11] + db[1];
            e[b] = (m0 >= m1) ? 1 : 0;
        }
    }
}

// ---------------- conv2 (skips exited samples) ------------------------------
__global__ void conv2_kernel(const float* __restrict__ h1,
                             const float* __restrict__ w,
                             const float* __restrict__ bias,
                             float* __restrict__ h2,
                             const int* __restrict__ e1)
{
    int b = blockIdx.x;
    if (e1[b]) return;
    __shared__ float hs[8450];
    const float* hb = h1 + (size_t)b * K1;
    for (int i = threadIdx.x; i < 8450; i += blockDim.x) hs[i] = hb[i];
    __syncthreads();

    int t = threadIdx.x;
    if (t >= 125) return;
    int pos = t / 5;
    int ocg = (t % 5) * 10;
    int py = pos / 5, px = pos % 5;
    int Y = 2 * py, X = 2 * px;

    float acc0[10], acc1[10], acc2[10], acc3[10];
    #pragma unroll
    for (int o = 0; o < 10; o++) { acc0[o]=0.f; acc1[o]=0.f; acc2[o]=0.f; acc3[o]=0.f; }

    for (int ic = 0; ic < 50; ic++) {
        const float* hc = hs + ic * 169;
        #pragma unroll
        for (int ky = 0; ky < 3; ky++)
            #pragma unroll
            for (int kx = 0; kx < 3; kx++) {
                float h00 = hc[(Y + ky) * 13 + X + kx];
                float h01 = hc[(Y + ky) * 13 + X + 1 + kx];
                float h10 = hc[(Y + 1 + ky) * 13 + X + kx];
                float h11 = hc[(Y + 1 + ky) * 13 + X + 1 + kx];
                int widx = ic * 9 + ky * 3 + kx;
                #pragma unroll
                for (int o = 0; o < 10; o++) {
                    float wv = __ldg(&w[(ocg + o) * 450 + widx]);
                    acc0[o] += h00 * wv;
                    acc1[o] += h01 * wv;
                    acc2[o] += h10 * wv;
                    acc3[o] += h11 * wv;
                }
            }
    }
    #pragma unroll
    for (int o = 0; o < 10; o++) {
        float m = fmaxf(fmaxf(acc0[o], acc1[o]), fmaxf(acc2[o], acc3[o]));
        m += __ldg(&bias[ocg + o]);
        h2[(size_t)b * K2 + (ocg + o) * 25 + pos] = fmaxf(m, 0.f);
    }
}

// ---------------- conv3 (skips samples exiting at 1 or 2) -------------------
__global__ void conv3_kernel(const float* __restrict__ h2,
                             const float* __restrict__ w,
                             const float* __restrict__ bias,
                             float* __restrict__ f3,
                             const int* __restrict__ e1,
                             const int* __restrict__ e2)
{
    int b = blockIdx.x;
    if (e1[b] || e2[b]) return;
    __shared__ float hs[1250];
    const float* hb = h2 + (size_t)b * K2;
    for (int i = threadIdx.x; i < 1250; i += blockDim.x) hs[i] = hb[i];
    __syncthreads();

    int oc = threadIdx.x;
    if (oc >= 50) return;
    float a0 = 0.f, a1 = 0.f, a2 = 0.f, a3 = 0.f;
    for (int ic = 0; ic < 50; ic++) {
        const float* hc = hs + ic * 25;
        #pragma unroll
        for (int ky = 0; ky < 3; ky++)
            #pragma unroll
            for (int kx = 0; kx < 3; kx++) {
                float wv = __ldg(&w[oc * 450 + ic * 9 + ky * 3 + kx]);
                a0 += hc[ky * 5 + kx] * wv;
                a1 += hc[ky * 5 + kx + 1] * wv;
                a2 += hc[(ky + 1) * 5 + kx] * wv;
                a3 += hc[(ky + 1) * 5 + kx + 1] * wv;
            }
    }
    float m = fmaxf(fmaxf(a0, a1), fmaxf(a2, a3)) + __ldg(&bias[oc]);
    f3[b * 50 + oc] = fmaxf(m, 0.f);
}

// ========= stage3 fused: o3 = relu(f3 @ l1ᵀ + b1) @ l2ᵀ + b2 ================
#define S3_G 32
#define S3_SMEM ((25000 + 5000 + 500 + S3_G * 50 + S3_G * 500) * 4)  // ~192.4 KB

__global__ __launch_bounds__(256) void stage3_kernel(
    const float* __restrict__ f3,
    const float* __restrict__ l1w, const float* __restrict__ l1b,
    const float* __restrict__ l2w, const float* __restrict__ l2b,
    float* __restrict__ o3)
{
    extern __shared__ float sm[];
    float* w1  = sm;                  // [500*50]
    float* w2  = sm + 25000;          // [10*500]
    float* b1  = sm + 30000;          // [500]
    float* fs  = sm + 30500;          // [32*50]
    float* hid = sm + 32100;          // [32*500]
    int tid = threadIdx.x;
    int b0 = blockIdx.x * S3_G;

    for (int i = tid; i < 25000; i += 256) w1[i] = l1w[i];
    for (int i = tid; i < 5000;  i += 256) w2[i] = l2w[i];
    for (int i = tid; i < 500;   i += 256) b1[i] = l1b[i];
    for (int i = tid; i < S3_G * 50; i += 256) fs[i] = f3[b0 * 50 + i];
    __syncthreads();

    for (int hh = tid; hh < S3_G * 500; hh += 256) {
        int s = hh / 500, j = hh - s * 500;
        float a = b1[j];
        const float* fr = fs + s * 50;
        const float* wr = w1 + j * 50;
        #pragma unroll 10
        for (int k = 0; k < 50; k++) a += fr[k] * wr[k];
        hid[hh] = fmaxf(a, 0.f);
    }
    __syncthreads();

    for (int oo = tid; oo < S3_G * 10; oo += 256) {
        int s = oo / 10, n = oo - s * 10;
        float a = __ldg(&l2b[n]);
        const float* hr = hid + s * 500;
        const float* wr = w2 + n * 500;
        #pragma unroll 4
        for (int j = 0; j < 500; j++) a += hr[j] * wr[j];
        o3[(b0 + s) * 10 + n] = a;
    }
}

// ---------------- select + log_softmax -------------------------------------
__global__ void final_kernel(const int* __restrict__ e1, const int* __restrict__ e2,
                             const float* __restrict__ o1, const float* __restrict__ o2,
                             const float* __restrict__ o3, float* __restrict__ out)
{
    int b = blockIdx.x * blockDim.x + threadIdx.x;
    if (b >= BATCH) return;
    const float* s = e1[b] ? (o1 + b * 10) : (e2[b] ? (o2 + b * 10) : (o3 + b * 10));
    float v[10], mx = -1e30f;
    #pragma unroll
    for (int i = 0; i < 10; i++) { v[i] = s[i]; mx = fmaxf(mx, v[i]); }
    float sum = 0.f;
    #pragma unroll
    for (int i = 0; i < 10; i++) sum += expf(v[i] - mx);
    float l = logf(sum);
    #pragma unroll
    for (int i = 0; i < 10; i++) out[b * 10 + i] = v[i] - mx - l;
}

// ---------------- launch ----------------------------------------------------
extern "C" void kernel_launch(void* const* d_in, const int* in_sizes, int n_in,
                              void* d_out, int out_size)
{
    const float* x      = (const float*)d_in[0];
    const float* c1_w   = (const float*)d_in[1];
    const float* c1_b   = (const float*)d_in[2];
    const float* c2_w   = (const float*)d_in[3];
    const float* c2_b   = (const float*)d_in[4];
    const float* c3_w   = (const float*)d_in[5];
    const float* c3_b   = (const float*)d_in[6];
    const float* l1c1_w = (const float*)d_in[7];
    const float* l1c1_b = (const float*)d_in[8];
    const float* l2c1_w = (const float*)d_in[9];
    const float* l2c1_b = (const float*)d_in[10];
    const float* l1c2_w = (const float*)d_in[11];
    const float* l1c2_b = (const float*)d_in[12];
    const float* l2c2_w = (const float*)d_in[13];
    const float* l2c2_b = (const float*)d_in[14];
    const float* l1_w   = (const float*)d_in[15];
    const float* l1_b   = (const float*)d_in[16];
    const float* l2_w   = (const float*)d_in[17];
    const float* l2_b   = (const float*)d_in[18];
    const float* d1_w   = (const float*)d_in[19];
    const float* d1_b   = (const float*)d_in[20];
    const float* d2_w   = (const float*)d_in[21];
    const float* d2_b   = (const float*)d_in[22];
    float* out = (float*)d_out;

    float *h1, *h2, *f3, *o1, *o2, *o3, *wc1, *bc1, *wc2, *bc2;
    int *e1, *e2;
    cudaGetSymbolAddress((void**)&h1,  g_h1);
    cudaGetSymbolAddress((void**)&h2,  g_h2);
    cudaGetSymbolAddress((void**)&f3,  g_f3);
    cudaGetSymbolAddress((void**)&o1,  g_o1);
    cudaGetSymbolAddress((void**)&o2,  g_o2);
    cudaGetSymbolAddress((void**)&o3,  g_o3);
    cudaGetSymbolAddress((void**)&e1,  g_e1);
    cudaGetSymbolAddress((void**)&e2,  g_e2);
    cudaGetSymbolAddress((void**)&wc1, g_wc1);
    cudaGetSymbolAddress((void**)&bc1, g_bc1);
    cudaGetSymbolAddress((void**)&wc2, g_wc2);
    cudaGetSymbolAddress((void**)&bc2, g_bc2);

    static int attr_set = 0;
    if (!attr_set) {
        cudaFuncSetAttribute(stagehead_kernel,
                             cudaFuncAttributeMaxDynamicSharedMemorySize, SH_SMEM);
        cudaFuncSetAttribute(stage3_kernel,
                             cudaFuncAttributeMaxDynamicSharedMemorySize, S3_SMEM);
        attr_set = 1;
    }

    // collapse the relu-free double linears: Wc = l2 @ l1, bc = l2 @ b1 + b2
    combine_kernel<<<(K1 + 255) / 256, 256>>>(l1c1_w, l1c1_b, l2c1_w, l2c1_b, K1, wc1, bc1);
    combine_kernel<<<(K2 + 255) / 256, 256>>>(l1c2_w, l1c2_b, l2c2_w, l2c2_b, K2, wc2, bc2);

    // stage 1
    conv1_kernel<<<BATCH, 256>>>(x, c1_w, c1_b, h1);
    stagehead_kernel<<<BATCH / SH_G, 256, SH_SMEM>>>(h1, K1, wc1, bc1, d1_w, d1_b, o1, e1);

    // stage 2
    conv2_kernel<<<BATCH, 128>>>(h1, c2_w, c2_b, h2, e1);
    stagehead_kernel<<<BATCH / SH_G, 256, SH_SMEM>>>(h2, K2, wc2, bc2, d2_w, d2_b, o2, e2);

    // stage 3
    conv3_kernel<<<BATCH, 64>>>(h2, c3_w, c3_b, f3, e1, e2);
    stage3_kernel<<<BATCH / S3_G, 256, S3_SMEM>>>(f3, l1_w, l1_b, l2_w, l2_b, o3);

    final_kernel<<<(BATCH + 255) / 256, 256>>>(e1, e2, o1, o2, o3, out);
}

// round 5
// speedup vs baseline: 4.4116x; 1.2667x over previous
#include <cuda_runtime.h>
#include <math.h>
#include <stdint.h>

#define BATCH 4096
#define K1 8450
#define K2 1250
#define KP1P 8704          // h1 row pitch (17 * 512)
#define KP2P 1536          // h2 row pitch (3 * 512)

// ---------------- scratch (device globals; zero-initialized) ---------------
// pads (k >= K per row) are never written -> stay zero from static init
__device__ float g_h1[(size_t)BATCH * KP1P];
__device__ float g_h2[(size_t)BATCH * KP2P];
__device__ float g_f3[BATCH * 50];
__device__ float g_o1[BATCH * 10];
__device__ float g_o2[BATCH * 10];
__device__ float g_o3[BATCH * 10];
__device__ int   g_e1[BATCH];
__device__ int   g_e2[BATCH];
__device__ float g_W1[12 * KP1P];   // rows 0-9: l2c1@l1c1 combined; 10-11: d1_w
__device__ float g_W2[12 * KP2P];
__device__ float g_b1c[12];         // 0-9: combined bias; 10-11: d1_b
__device__ float g_b2c[12];
__device__ float2 g_wpk2[50 * 450]; // conv2 weights duplicated (w,w)

// ========== combine: W12 rows 0-9 = l2@l1 (padded); rows 10-11 = dw ========
__global__ __launch_bounds__(256) void combine_kernel(
    const float* __restrict__ l1, const float* __restrict__ b1,
    const float* __restrict__ l2, const float* __restrict__ b2,
    const float* __restrict__ dw, const float* __restrict__ db,
    int K, int Kp, float* __restrict__ W12, float* __restrict__ bc12)
{
    __shared__ float l2T[500 * 12];
    int tid = threadIdx.x;
    for (int i = tid; i < 5000; i += 256) {
        int j = i / 500, r = i - j * 500;
        l2T[r * 12 + j] = l2[i];
    }
    for (int r = tid; r < 500; r += 256) { l2T[r * 12 + 10] = 0.f; l2T[r * 12 + 11] = 0.f; }
    __syncthreads();

    int k = blockIdx.x * 256 + tid;
    if (k < Kp) {
        if (k < K) {
            float acc[10];
            #pragma unroll
            for (int j = 0; j < 10; j++) acc[j] = 0.f;
            for (int r = 0; r < 500; r++) {
                float a = __ldg(&l1[(size_t)r * K + k]);
                float4 w0 = *(const float4*)&l2T[r * 12];
                float4 w1 = *(const float4*)&l2T[r * 12 + 4];
                float2 w2 = *(const float2*)&l2T[r * 12 + 8];
                acc[0] += a * w0.x; acc[1] += a * w0.y; acc[2] += a * w0.z; acc[3] += a * w0.w;
                acc[4] += a * w1.x; acc[5] += a * w1.y; acc[6] += a * w1.z; acc[7] += a * w1.w;
                acc[8] += a * w2.x; acc[9] += a * w2.y;
            }
            #pragma unroll
            for (int j = 0; j < 10; j++) W12[(size_t)j * Kp + k] = acc[j];
            W12[(size_t)10 * Kp + k] = __ldg(&dw[k]);
            W12[(size_t)11 * Kp + k] = __ldg(&dw[K + k]);
        } else {
            #pragma unroll
            for (int j = 0; j < 12; j++) W12[(size_t)j * Kp + k] = 0.f;
        }
    }
    if (blockIdx.x == 0) {
        if (tid < 10) {
            float a = b2[tid];
            for (int r = 0; r < 500; r++) a += l2[tid * 500 + r] * b1[r];
            bc12[tid] = a;
        } else if (tid < 12) {
            bc12[tid] = db[tid - 10];
        }
    }
}

// ------------- pack conv2 weights into duplicated float2 --------------------
__global__ void pack_w2_kernel(const float* __restrict__ w, float2* __restrict__ wpk)
{
    int i = blockIdx.x * blockDim.x + threadIdx.x;
    if (i < 50 * 450) { float v = w[i]; wpk[i] = make_float2(v, v); }
}

// ---------------- conv1: [B,1,28,28] -> relu+pool2 -> [B,50,13,13] ---------
__global__ void conv1_kernel(const float* __restrict__ x,
                             const float* __restrict__ w,
                             const float* __restrict__ bias,
                             float* __restrict__ h1)
{
    int b = blockIdx.x;
    __shared__ float xs[28 * 28];
    __shared__ float ws[50 * 9];
    __shared__ float bs[50];
    const float* xb = x + (size_t)b * 784;
    for (int i = threadIdx.x; i < 784; i += blockDim.x) xs[i] = xb[i];
    for (int i = threadIdx.x; i < 450; i += blockDim.x) ws[i] = w[i];
    for (int i = threadIdx.x; i < 50;  i += blockDim.x) bs[i] = bias[i];
    __syncthreads();

    for (int idx = threadIdx.x; idx < 8450; idx += blockDim.x) {
        int oc = idx / 169;
        int p  = idx % 169;
        int py = p / 13, px = p % 13;
        const float* wk = ws + oc * 9;
        float m = -1e30f;
        #pragma unroll
        for (int dy = 0; dy < 2; dy++)
            #pragma unroll
            for (int dx = 0; dx < 2; dx++) {
                int y = 2 * py + dy, xx = 2 * px + dx;
                float s = 0.f;
                #pragma unroll
                for (int ky = 0; ky < 3; ky++)
                    #pragma unroll
                    for (int kx = 0; kx < 3; kx++)
                        s += xs[(y + ky) * 28 + xx + kx] * wk[ky * 3 + kx];
                m = fmaxf(m, s);
            }
        m += bs[oc];
        h1[(size_t)b * KP1P + idx] = fmaxf(m, 0.f);
    }
}

// ====== stagehead v2: 12 dots per sample (10 out + 2 exit), padded K ========
// 256 thr / 8 warps; warp handles 2 samples; G=16 samples/block; chunk 512.
#define SH_G 16
#define SH_CK 512
#define SH_SMEM ((12 * SH_CK + SH_G * SH_CK) * 4)   // 56 KB

__global__ __launch_bounds__(256) void stagehead_kernel(
    const float* __restrict__ f, int Kp,
    const float* __restrict__ W12, const float* __restrict__ bc12,
    float* __restrict__ o, int* __restrict__ e)
{
    extern __shared__ float sh[];
    float* ws = sh;                     // [12][SH_CK]
    float* hs = sh + 12 * SH_CK;        // [SH_G][SH_CK]
    const int tid = threadIdx.x, lane = tid & 31, wid = tid >> 5;
    const int b0 = blockIdx.x * SH_G;
    const int s0 = wid * 2, s1 = s0 + 1;

    float acc0[12], acc1[12];
    #pragma unroll
    for (int j = 0; j < 12; j++) { acc0[j] = 0.f; acc1[j] = 0.f; }

    const int nchunks = Kp / SH_CK;
    for (int c = 0; c < nchunks; c++) {
        const int kc = c * SH_CK;
        // stage weights: 12*128 float4 (aligned: Kp mult of 512)
        for (int i = tid; i < 12 * 128; i += 256) {
            int j = i >> 7, k4 = (i & 127) * 4;
            *(float4*)&ws[j * SH_CK + k4] = *(const float4*)&W12[(size_t)j * Kp + kc + k4];
        }
        // stage features: 16*128 float4
        for (int i = tid; i < SH_G * 128; i += 256) {
            int s = i >> 7, k4 = (i & 127) * 4;
            *(float4*)&hs[s * SH_CK + k4] = *(const float4*)&f[(size_t)(b0 + s) * Kp + kc + k4];
        }
        __syncthreads();

        #pragma unroll
        for (int it = 0; it < 4; it++) {
            const int kk = it * 128 + lane * 4;
            float4 f0 = *(float4*)&hs[s0 * SH_CK + kk];
            float4 f1 = *(float4*)&hs[s1 * SH_CK + kk];
            #pragma unroll
            for (int j = 0; j < 12; j++) {
                float4 w = *(float4*)&ws[j * SH_CK + kk];
                acc0[j] = fmaf(f0.x, w.x, fmaf(f0.y, w.y, fmaf(f0.z, w.z, fmaf(f0.w, w.w, acc0[j]))));
                acc1[j] = fmaf(f1.x, w.x, fmaf(f1.y, w.y, fmaf(f1.z, w.z, fmaf(f1.w, w.w, acc1[j]))));
            }
        }
        __syncthreads();
    }

    #pragma unroll
    for (int j = 0; j < 12; j++) {
        #pragma unroll
        for (int off = 16; off; off >>= 1) {
            acc0[j] += __shfl_xor_sync(0xffffffffu, acc0[j], off);
            acc1[j] += __shfl_xor_sync(0xffffffffu, acc1[j], off);
        }
    }
    if (lane == 0) {
        int ba = b0 + s0, bb = b0 + s1;
        #pragma unroll
        for (int j = 0; j < 10; j++) {
            o[ba * 10 + j] = acc0[j] + bc12[j];
            o[bb * 10 + j] = acc1[j] + bc12[j];
        }
        e[ba] = (acc0[10] + bc12[10] >= acc0[11] + bc12[11]) ? 1 : 0;
        e[bb] = (acc1[10] + bc12[10] >= acc1[11] + bc12[11]) ? 1 : 0;
    }
}

// ---------------- conv2 (f32x2 packed FMA; skips exited samples) -----------
__global__ void conv2_kernel(const float* __restrict__ h1,
                             const float2* __restrict__ wpk,
                             const float* __restrict__ bias,
                             float* __restrict__ h2,
                             const int* __restrict__ e1)
{
    int b = blockIdx.x;
    if (e1[b]) return;
    __shared__ float hs[8450];
    const float* hb = h1 + (size_t)b * KP1P;
    for (int i = threadIdx.x; i < 8450; i += blockDim.x) hs[i] = hb[i];
    __syncthreads();

    int t = threadIdx.x;
    if (t >= 125) return;
    int pos = t / 5;
    int ocg = (t % 5) * 10;
    int py = pos / 5, px = pos % 5;
    int Y = 2 * py, X = 2 * px;

    unsigned long long aT[10], aB[10];   // packed (h00,h01) / (h10,h11) accumulators
    #pragma unroll
    for (int o = 0; o < 10; o++) { aT[o] = 0ULL; aB[o] = 0ULL; }

    for (int ic = 0; ic < 50; ic++) {
        const float* hc = hs + ic * 169;
        #pragma unroll
        for (int ky = 0; ky < 3; ky++)
            #pragma unroll
            for (int kx = 0; kx < 3; kx++) {
                float h00 = hc[(Y + ky) * 13 + X + kx];
                float h01 = hc[(Y + ky) * 13 + X + 1 + kx];
                float h10 = hc[(Y + 1 + ky) * 13 + X + kx];
                float h11 = hc[(Y + 1 + ky) * 13 + X + 1 + kx];
                unsigned long long pt, pb;
                asm("mov.b64 %0, {%1, %2};" : "=l"(pt)
                    : "r"(__float_as_uint(h00)), "r"(__float_as_uint(h01)));
                asm("mov.b64 %0, {%1, %2};" : "=l"(pb)
                    : "r"(__float_as_uint(h10)), "r"(__float_as_uint(h11)));
                int widx = ic * 9 + ky * 3 + kx;
                #pragma unroll
                for (int o = 0; o < 10; o++) {
                    unsigned long long w2 =
                        __ldg((const unsigned long long*)&wpk[(ocg + o) * 450 + widx]);
                    asm("fma.rn.f32x2 %0, %1, %2, %0;" : "+l"(aT[o]) : "l"(pt), "l"(w2));
                    asm("fma.rn.f32x2 %0, %1, %2, %0;" : "+l"(aB[o]) : "l"(pb), "l"(w2));
                }
            }
    }
    #pragma unroll
    for (int o = 0; o < 10; o++) {
        unsigned int u0, u1, u2, u3;
        asm("mov.b64 {%0, %1}, %2;" : "=r"(u0), "=r"(u1) : "l"(aT[o]));
        asm("mov.b64 {%0, %1}, %2;" : "=r"(u2), "=r"(u3) : "l"(aB[o]));
        float m = fmaxf(fmaxf(__uint_as_float(u0), __uint_as_float(u1)),
                        fmaxf(__uint_as_float(u2), __uint_as_float(u3)));
        m += __ldg(&bias[ocg + o]);
        h2[(size_t)b * KP2P + (ocg + o) * 25 + pos] = fmaxf(m, 0.f);
    }
}

// ---------------- conv3 (skips samples exiting at 1 or 2) -------------------
__global__ void conv3_kernel(const float* __restrict__ h2,
                             const float* __restrict__ w,
                             const float* __restrict__ bias,
                             float* __restrict__ f3,
                             const int* __restrict__ e1,
                             const int* __restrict__ e2)
{
    int b = blockIdx.x;
    if (e1[b] || e2[b]) return;
    __shared__ float hs[1250];
    const float* hb = h2 + (size_t)b * KP2P;
    for (int i = threadIdx.x; i < 1250; i += blockDim.x) hs[i] = hb[i];
    __syncthreads();

    int oc = threadIdx.x;
    if (oc >= 50) return;
    float a0 = 0.f, a1 = 0.f, a2 = 0.f, a3 = 0.f;
    for (int ic = 0; ic < 50; ic++) {
        const float* hc = hs + ic * 25;
        #pragma unroll
        for (int ky = 0; ky < 3; ky++)
            #pragma unroll
            for (int kx = 0; kx < 3; kx++) {
                float wv = __ldg(&w[oc * 450 + ic * 9 + ky * 3 + kx]);
                a0 += hc[ky * 5 + kx] * wv;
                a1 += hc[ky * 5 + kx + 1] * wv;
                a2 += hc[(ky + 1) * 5 + kx] * wv;
                a3 += hc[(ky + 1) * 5 + kx + 1] * wv;
            }
    }
    float m = fmaxf(fmaxf(a0, a1), fmaxf(a2, a3)) + __ldg(&bias[oc]);
    f3[b * 50 + oc] = fmaxf(m, 0.f);
}

// ========= stage3 fused: o3 = relu(f3 @ l1ᵀ + b1) @ l2ᵀ + b2 ================
#define S3_G 32
#define S3_SMEM ((25000 + 5000 + 500 + S3_G * 50 + S3_G * 500) * 4)

__global__ __launch_bounds__(256) void stage3_kernel(
    const float* __restrict__ f3,
    const float* __restrict__ l1w, const float* __restrict__ l1b,
    const float* __restrict__ l2w, const float* __restrict__ l2b,
    float* __restrict__ o3)
{
    extern __shared__ float sm[];
    float* w1  = sm;
    float* w2  = sm + 25000;
    float* b1  = sm + 30000;
    float* fs  = sm + 30500;
    float* hid = sm + 32100;
    int tid = threadIdx.x;
    int b0 = blockIdx.x * S3_G;

    for (int i = tid; i < 25000; i += 256) w1[i] = l1w[i];
    for (int i = tid; i < 5000;  i += 256) w2[i] = l2w[i];
    for (int i = tid; i < 500;   i += 256) b1[i] = l1b[i];
    for (int i = tid; i < S3_G * 50; i += 256) fs[i] = f3[b0 * 50 + i];
    __syncthreads();

    for (int hh = tid; hh < S3_G * 500; hh += 256) {
        int s = hh / 500, j = hh - s * 500;
        float a = b1[j];
        const float* fr = fs + s * 50;
        const float* wr = w1 + j * 50;
        #pragma unroll 10
        for (int k = 0; k < 50; k++) a += fr[k] * wr[k];
        hid[hh] = fmaxf(a, 0.f);
    }
    __syncthreads();

    for (int oo = tid; oo < S3_G * 10; oo += 256) {
        int s = oo / 10, n = oo - s * 10;
        float a = __ldg(&l2b[n]);
        const float* hr = hid + s * 500;
        const float* wr = w2 + n * 500;
        #pragma unroll 4
        for (int j = 0; j < 500; j++) a += hr[j] * wr[j];
        o3[(b0 + s) * 10 + n] = a;
    }
}

// ---------------- select + log_softmax -------------------------------------
__global__ void final_kernel(const int* __restrict__ e1, const int* __restrict__ e2,
                             const float* __restrict__ o1, const float* __restrict__ o2,
                             const float* __restrict__ o3, float* __restrict__ out)
{
    int b = blockIdx.x * blockDim.x + threadIdx.x;
    if (b >= BATCH) return;
    const float* s = e1[b] ? (o1 + b * 10) : (e2[b] ? (o2 + b * 10) : (o3 + b * 10));
    float v[10], mx = -1e30f;
    #pragma unroll
    for (int i = 0; i < 10; i++) { v[i] = s[i]; mx = fmaxf(mx, v[i]); }
    float sum = 0.f;
    #pragma unroll
    for (int i = 0; i < 10; i++) sum += expf(v[i] - mx);
    float l = logf(sum);
    #pragma unroll
    for (int i = 0; i < 10; i++) out[b * 10 + i] = v[i] - mx - l;
}

// ---------------- launch ----------------------------------------------------
extern "C" void kernel_launch(void* const* d_in, const int* in_sizes, int n_in,
                              void* d_out, int out_size)
{
    const float* x      = (const float*)d_in[0];
    const float* c1_w   = (const float*)d_in[1];
    const float* c1_b   = (const float*)d_in[2];
    const float* c2_w   = (const float*)d_in[3];
    const float* c2_b   = (const float*)d_in[4];
    const float* c3_w   = (const float*)d_in[5];
    const float* c3_b   = (const float*)d_in[6];
    const float* l1c1_w = (const float*)d_in[7];
    const float* l1c1_b = (const float*)d_in[8];
    const float* l2c1_w = (const float*)d_in[9];
    const float* l2c1_b = (const float*)d_in[10];
    const float* l1c2_w = (const float*)d_in[11];
    const float* l1c2_b = (const float*)d_in[12];
    const float* l2c2_w = (const float*)d_in[13];
    const float* l2c2_b = (const float*)d_in[14];
    const float* l1_w   = (const float*)d_in[15];
    const float* l1_b   = (const float*)d_in[16];
    const float* l2_w   = (const float*)d_in[17];
    const float* l2_b   = (const float*)d_in[18];
    const float* d1_w   = (const float*)d_in[19];
    const float* d1_b   = (const float*)d_in[20];
    const float* d2_w   = (const float*)d_in[21];
    const float* d2_b   = (const float*)d_in[22];
    float* out = (float*)d_out;

    float *h1, *h2, *f3, *o1, *o2, *o3, *W1, *W2, *b1c, *b2c;
    float2* wpk2;
    int *e1, *e2;
    cudaGetSymbolAddress((void**)&h1,  g_h1);
    cudaGetSymbolAddress((void**)&h2,  g_h2);
    cudaGetSymbolAddress((void**)&f3,  g_f3);
    cudaGetSymbolAddress((void**)&o1,  g_o1);
    cudaGetSymbolAddress((void**)&o2,  g_o2);
    cudaGetSymbolAddress((void**)&o3,  g_o3);
    cudaGetSymbolAddress((void**)&e1,  g_e1);
    cudaGetSymbolAddress((void**)&e2,  g_e2);
    cudaGetSymbolAddress((void**)&W1,  g_W1);
    cudaGetSymbolAddress((void**)&W2,  g_W2);
    cudaGetSymbolAddress((void**)&b1c, g_b1c);
    cudaGetSymbolAddress((void**)&b2c, g_b2c);
    cudaGetSymbolAddress((void**)&wpk2, g_wpk2);

    static int attr_set = 0;
    if (!attr_set) {
        cudaFuncSetAttribute(stagehead_kernel,
                             cudaFuncAttributeMaxDynamicSharedMemorySize, SH_SMEM);
        cudaFuncSetAttribute(stage3_kernel,
                             cudaFuncAttributeMaxDynamicSharedMemorySize, S3_SMEM);
        attr_set = 1;
    }

    // prep: combined head weights (padded, incl. exit rows) + packed conv2 w
    combine_kernel<<<(KP1P + 255) / 256, 256>>>(l1c1_w, l1c1_b, l2c1_w, l2c1_b,
                                                d1_w, d1_b, K1, KP1P, W1, b1c);
    combine_kernel<<<(KP2P + 255) / 256, 256>>>(l1c2_w, l1c2_b, l2c2_w, l2c2_b,
                                                d2_w, d2_b, K2, KP2P, W2, b2c);
    pack_w2_kernel<<<(50 * 450 + 255) / 256, 256>>>(c2_w, wpk2);

    // stage 1
    conv1_kernel<<<BATCH, 256>>>(x, c1_w, c1_b, h1);
    stagehead_kernel<<<BATCH / SH_G, 256, SH_SMEM>>>(h1, KP1P, W1, b1c, o1, e1);

    // stage 2
    conv2_kernel<<<BATCH, 128>>>(h1, wpk2, c2_b, h2, e1);
    stagehead_kernel<<<BATCH / SH_G, 256, SH_SMEM>>>(h2, KP2P, W2, b2c, o2, e2);

    // stage 3
    conv3_kernel<<<BATCH, 64>>>(h2, c3_w, c3_b, f3, e1, e2);
    stage3_kernel<<<BATCH / S3_G, 256, S3_SMEM>>>(f3, l1_w, l1_b, l2_w, l2_b, o3);

    final_kernel<<<(BATCH + 255) / 256, 256>>>(e1, e2, o1, o2, o3, out);
}

// round 6
// speedup vs baseline: 6.7543x; 1.5310x over previous
#include <cuda_runtime.h>
#include <math.h>
#include <stdint.h>

#define BATCH 4096
#define K1 8450
#define K2 1250
#define KP1P 8704          // h1 row pitch (17 * 512)
#define KP2P 1536          // h2 row pitch (3 * 512)

// ---------------- scratch (device globals; zero-initialized) ---------------
__device__ float g_h1[(size_t)BATCH * KP1P];
__device__ float g_h2[(size_t)BATCH * KP2P];
__device__ float g_f3[BATCH * 50];
__device__ float g_o1[BATCH * 10];
__device__ float g_o2[BATCH * 10];
__device__ float g_o3[BATCH * 10];
__device__ int   g_e1[BATCH];
__device__ int   g_e2[BATCH];
__device__ float g_W1[12 * KP1P];   // rows 0-9: l2c1@l1c1 combined; 10-11: d1_w
__device__ float g_W2[12 * KP2P];
__device__ float g_b1c[12];
__device__ float g_b2c[12];
__device__ float2 g_wpk1[50 * 9];    // conv1 weights duplicated (w,w)
__device__ float2 g_wpk2[50 * 450];  // conv2 weights, ic-major [ic][oc][9], dup

// ========== combine: W12 rows 0-9 = l2@l1 (padded); rows 10-11 = dw ========
__global__ __launch_bounds__(256) void combine_kernel(
    const float* __restrict__ l1, const float* __restrict__ b1,
    const float* __restrict__ l2, const float* __restrict__ b2,
    const float* __restrict__ dw, const float* __restrict__ db,
    int K, int Kp, float* __restrict__ W12, float* __restrict__ bc12)
{
    __shared__ float l2T[500 * 12];
    int tid = threadIdx.x;
    for (int i = tid; i < 5000; i += 256) {
        int j = i / 500, r = i - j * 500;
        l2T[r * 12 + j] = l2[i];
    }
    for (int r = tid; r < 500; r += 256) { l2T[r * 12 + 10] = 0.f; l2T[r * 12 + 11] = 0.f; }
    __syncthreads();

    int k = blockIdx.x * 256 + tid;
    if (k < Kp) {
        if (k < K) {
            float acc[10];
            #pragma unroll
            for (int j = 0; j < 10; j++) acc[j] = 0.f;
            for (int r = 0; r < 500; r++) {
                float a = __ldg(&l1[(size_t)r * K + k]);
                float4 w0 = *(const float4*)&l2T[r * 12];
                float4 w1 = *(const float4*)&l2T[r * 12 + 4];
                float2 w2 = *(const float2*)&l2T[r * 12 + 8];
                acc[0] += a * w0.x; acc[1] += a * w0.y; acc[2] += a * w0.z; acc[3] += a * w0.w;
                acc[4] += a * w1.x; acc[5] += a * w1.y; acc[6] += a * w1.z; acc[7] += a * w1.w;
                acc[8] += a * w2.x; acc[9] += a * w2.y;
            }
            #pragma unroll
            for (int j = 0; j < 10; j++) W12[(size_t)j * Kp + k] = acc[j];
            W12[(size_t)10 * Kp + k] = __ldg(&dw[k]);
            W12[(size_t)11 * Kp + k] = __ldg(&dw[K + k]);
        } else {
            #pragma unroll
            for (int j = 0; j < 12; j++) W12[(size_t)j * Kp + k] = 0.f;
        }
    }
    if (blockIdx.x == 0) {
        if (tid < 10) {
            float a = b2[tid];
            for (int r = 0; r < 500; r++) a += l2[tid * 500 + r] * b1[r];
            bc12[tid] = a;
        } else if (tid < 12) {
            bc12[tid] = db[tid - 10];
        }
    }
}

// ------------- weight packers -----------------------------------------------
__global__ void pack_w1_kernel(const float* __restrict__ w, float2* __restrict__ wpk)
{
    int i = blockIdx.x * blockDim.x + threadIdx.x;
    if (i < 50 * 9) { float v = w[i]; wpk[i] = make_float2(v, v); }
}
// conv2: reorder [oc][ic][9] -> [ic][oc][9], duplicated
__global__ void pack_w2_kernel(const float* __restrict__ w, float2* __restrict__ wpk)
{
    int i = blockIdx.x * blockDim.x + threadIdx.x;
    if (i < 50 * 450) {
        int oc = i / 450, r = i - oc * 450;
        int ic = r / 9, k = r - ic * 9;
        float v = w[i];
        wpk[ic * 450 + oc * 9 + k] = make_float2(v, v);
    }
}

// ---------------- conv1 v2: register patch + packed f32x2 -------------------
// block = 1 sample, 192 threads (169 active: one pool position each, all 50 oc)
__global__ __launch_bounds__(192) void conv1_kernel(
    const float* __restrict__ x, const float2* __restrict__ wpk,
    const float* __restrict__ bias, float* __restrict__ h1)
{
    int b = blockIdx.x;
    __shared__ float xs[784];
    __shared__ float2 ws[450];
    __shared__ float bs[50];
    int tid = threadIdx.x;
    {
        const float4* xb = (const float4*)(x + (size_t)b * 784);
        for (int i = tid; i < 196; i += 192) ((float4*)xs)[i] = xb[i];
        for (int i = tid; i < 450; i += 192) ws[i] = wpk[i];
        for (int i = tid; i < 50;  i += 192) bs[i] = bias[i];
    }
    __syncthreads();
    if (tid >= 169) return;

    const int py = tid / 13, px = tid % 13;
    const int Y = 2 * py, X = 2 * px;
    float p[4][4];
    #pragma unroll
    for (int r = 0; r < 4; r++)
        #pragma unroll
        for (int c = 0; c < 4; c++) p[r][c] = xs[(Y + r) * 28 + X + c];
    unsigned long long P[4][3];
    #pragma unroll
    for (int r = 0; r < 4; r++)
        #pragma unroll
        for (int k = 0; k < 3; k++)
            asm("mov.b64 %0, {%1, %2};" : "=l"(P[r][k])
                : "r"(__float_as_uint(p[r][k])), "r"(__float_as_uint(p[r][k + 1])));

    float* hb = h1 + (size_t)b * KP1P + tid;
    for (int oc = 0; oc < 50; oc++) {
        unsigned long long aT = 0ULL, aB = 0ULL;
        #pragma unroll
        for (int ky = 0; ky < 3; ky++)
            #pragma unroll
            for (int kx = 0; kx < 3; kx++) {
                unsigned long long w2 = *(const unsigned long long*)&ws[oc * 9 + ky * 3 + kx];
                asm("fma.rn.f32x2 %0, %1, %2, %0;" : "+l"(aT) : "l"(P[ky][kx]), "l"(w2));
                asm("fma.rn.f32x2 %0, %1, %2, %0;" : "+l"(aB) : "l"(P[ky + 1][kx]), "l"(w2));
            }
        unsigned int u0, u1, u2, u3;
        asm("mov.b64 {%0, %1}, %2;" : "=r"(u0), "=r"(u1) : "l"(aT));
        asm("mov.b64 {%0, %1}, %2;" : "=r"(u2), "=r"(u3) : "l"(aB));
        float m = fmaxf(fmaxf(__uint_as_float(u0), __uint_as_float(u1)),
                        fmaxf(__uint_as_float(u2), __uint_as_float(u3)));
        m += bs[oc];
        hb[oc * 169] = fmaxf(m, 0.f);
    }
}

// ====== stagehead: 12 dots per sample (10 out + 2 exit), padded K ===========
#define SH_G 16
#define SH_CK 512
#define SH_SMEM ((12 * SH_CK + SH_G * SH_CK) * 4)   // 56 KB

__global__ __launch_bounds__(256) void stagehead_kernel(
    const float* __restrict__ f, int Kp,
    const float* __restrict__ W12, const float* __restrict__ bc12,
    float* __restrict__ o, int* __restrict__ e)
{
    extern __shared__ float sh[];
    float* ws = sh;
    float* hs = sh + 12 * SH_CK;
    const int tid = threadIdx.x, lane = tid & 31, wid = tid >> 5;
    const int b0 = blockIdx.x * SH_G;
    const int s0 = wid * 2, s1 = s0 + 1;

    float acc0[12], acc1[12];
    #pragma unroll
    for (int j = 0; j < 12; j++) { acc0[j] = 0.f; acc1[j] = 0.f; }

    const int nchunks = Kp / SH_CK;
    for (int c = 0; c < nchunks; c++) {
        const int kc = c * SH_CK;
        for (int i = tid; i < 12 * 128; i += 256) {
            int j = i >> 7, k4 = (i & 127) * 4;
            *(float4*)&ws[j * SH_CK + k4] = *(const float4*)&W12[(size_t)j * Kp + kc + k4];
        }
        for (int i = tid; i < SH_G * 128; i += 256) {
            int s = i >> 7, k4 = (i & 127) * 4;
            *(float4*)&hs[s * SH_CK + k4] = *(const float4*)&f[(size_t)(b0 + s) * Kp + kc + k4];
        }
        __syncthreads();

        #pragma unroll
        for (int it = 0; it < 4; it++) {
            const int kk = it * 128 + lane * 4;
            float4 f0 = *(float4*)&hs[s0 * SH_CK + kk];
            float4 f1 = *(float4*)&hs[s1 * SH_CK + kk];
            #pragma unroll
            for (int j = 0; j < 12; j++) {
                float4 w = *(float4*)&ws[j * SH_CK + kk];
                acc0[j] = fmaf(f0.x, w.x, fmaf(f0.y, w.y, fmaf(f0.z, w.z, fmaf(f0.w, w.w, acc0[j]))));
                acc1[j] = fmaf(f1.x, w.x, fmaf(f1.y, w.y, fmaf(f1.z, w.z, fmaf(f1.w, w.w, acc1[j]))));
            }
        }
        __syncthreads();
    }

    #pragma unroll
    for (int j = 0; j < 12; j++) {
        #pragma unroll
        for (int off = 16; off; off >>= 1) {
            acc0[j] += __shfl_xor_sync(0xffffffffu, acc0[j], off);
            acc1[j] += __shfl_xor_sync(0xffffffffu, acc1[j], off);
        }
    }
    if (lane == 0) {
        int ba = b0 + s0, bb = b0 + s1;
        #pragma unroll
        for (int j = 0; j < 10; j++) {
            o[ba * 10 + j] = acc0[j] + bc12[j];
            o[bb * 10 + j] = acc1[j] + bc12[j];
        }
        e[ba] = (acc0[10] + bc12[10] >= acc0[11] + bc12[11]) ? 1 : 0;
        e[bb] = (acc1[10] + bc12[10] >= acc1[11] + bc12[11]) ? 1 : 0;
    }
}

// ---------------- conv2 v2: smem-staged ic-major weights, reg patch ---------
// 256 threads (250 active): osub = t/25 (5 oc each), pos = t%25
__global__ __launch_bounds__(256) void conv2_kernel(
    const float* __restrict__ h1, const float2* __restrict__ wpk,
    const float* __restrict__ bias, float* __restrict__ h2,
    const int* __restrict__ e1)
{
    int b = blockIdx.x;
    if (e1[b]) return;
    __shared__ float hs[8450];
    __shared__ float2 wb[2][450];
    __shared__ float bss[50];
    const int tid = threadIdx.x;
    {
        const float2* hb = (const float2*)(h1 + (size_t)b * KP1P);
        for (int i = tid; i < 4225; i += 256) ((float2*)hs)[i] = hb[i];
        for (int i = tid; i < 450; i += 256) wb[0][i] = wpk[i];
        for (int i = tid; i < 50;  i += 256) bss[i] = bias[i];
    }
    __syncthreads();

    const int osub = tid / 25, pos = tid % 25;       // osub 0..9 (t<250)
    const int oc0 = osub * 5;
    const int py = pos / 5, px = pos % 5;
    const int Y = 2 * py, X = 2 * px;
    const bool active = (tid < 250);

    unsigned long long aT[5], aB[5];
    #pragma unroll
    for (int j = 0; j < 5; j++) { aT[j] = 0ULL; aB[j] = 0ULL; }

    for (int ic = 0; ic < 50; ic++) {
        const int cur = ic & 1;
        // prefetch next ic weight slice (all 256 threads)
        if (ic + 1 < 50) {
            for (int i = tid; i < 450; i += 256)
                wb[cur ^ 1][i] = wpk[(ic + 1) * 450 + i];
        }
        if (active) {
            const float* hc = hs + ic * 169;
            float p[4][4];
            #pragma unroll
            for (int r = 0; r < 4; r++)
                #pragma unroll
                for (int c = 0; c < 4; c++) p[r][c] = hc[(Y + r) * 13 + X + c];
            unsigned long long P[4][3];
            #pragma unroll
            for (int r = 0; r < 4; r++)
                #pragma unroll
                for (int k = 0; k < 3; k++)
                    asm("mov.b64 %0, {%1, %2};" : "=l"(P[r][k])
                        : "r"(__float_as_uint(p[r][k])), "r"(__float_as_uint(p[r][k + 1])));
            #pragma unroll
            for (int ky = 0; ky < 3; ky++)
                #pragma unroll
                for (int kx = 0; kx < 3; kx++) {
                    const int wi = ky * 3 + kx;
                    #pragma unroll
                    for (int j = 0; j < 5; j++) {
                        unsigned long long w2 =
                            *(const unsigned long long*)&wb[cur][(oc0 + j) * 9 + wi];
                        asm("fma.rn.f32x2 %0, %1, %2, %0;" : "+l"(aT[j]) : "l"(P[ky][kx]), "l"(w2));
                        asm("fma.rn.f32x2 %0, %1, %2, %0;" : "+l"(aB[j]) : "l"(P[ky + 1][kx]), "l"(w2));
                    }
                }
        }
        __syncthreads();
    }

    if (active) {
        #pragma unroll
        for (int j = 0; j < 5; j++) {
            unsigned int u0, u1, u2, u3;
            asm("mov.b64 {%0, %1}, %2;" : "=r"(u0), "=r"(u1) : "l"(aT[j]));
            asm("mov.b64 {%0, %1}, %2;" : "=r"(u2), "=r"(u3) : "l"(aB[j]));
            float m = fmaxf(fmaxf(__uint_as_float(u0), __uint_as_float(u1)),
                            fmaxf(__uint_as_float(u2), __uint_as_float(u3)));
            m += bss[oc0 + j];
            h2[(size_t)b * KP2P + (oc0 + j) * 25 + pos] = fmaxf(m, 0.f);
        }
    }
}

// ---------------- conv3 (skips samples exiting at 1 or 2) -------------------
__global__ void conv3_kernel(const float* __restrict__ h2,
                             const float* __restrict__ w,
                             const float* __restrict__ bias,
                             float* __restrict__ f3,
                             const int* __restrict__ e1,
                             const int* __restrict__ e2)
{
    int b = blockIdx.x;
    if (e1[b] || e2[b]) return;
    __shared__ float hs[1250];
    const float* hb = h2 + (size_t)b * KP2P;
    for (int i = threadIdx.x; i < 1250; i += blockDim.x) hs[i] = hb[i];
    __syncthreads();

    int oc = threadIdx.x;
    if (oc >= 50) return;
    float a0 = 0.f, a1 = 0.f, a2 = 0.f, a3 = 0.f;
    for (int ic = 0; ic < 50; ic++) {
        const float* hc = hs + ic * 25;
        #pragma unroll
        for (int ky = 0; ky < 3; ky++)
            #pragma unroll
            for (int kx = 0; kx < 3; kx++) {
                float wv = __ldg(&w[oc * 450 + ic * 9 + ky * 3 + kx]);
                a0 += hc[ky * 5 + kx] * wv;
                a1 += hc[ky * 5 + kx + 1] * wv;
                a2 += hc[(ky + 1) * 5 + kx] * wv;
                a3 += hc[(ky + 1) * 5 + kx + 1] * wv;
            }
    }
    float m = fmaxf(fmaxf(a0, a1), fmaxf(a2, a3)) + __ldg(&bias[oc]);
    f3[b * 50 + oc] = fmaxf(m, 0.f);
}

// ========= stage3 fused: o3 = relu(f3 @ l1ᵀ + b1) @ l2ᵀ + b2 ================
#define S3_G 32
#define S3_SMEM ((25000 + 5000 + 500 + S3_G * 50 + S3_G * 500) * 4)

__global__ __launch_bounds__(256) void stage3_kernel(
    const float* __restrict__ f3,
    const float* __restrict__ l1w, const float* __restrict__ l1b,
    const float* __restrict__ l2w, const float* __restrict__ l2b,
    float* __restrict__ o3)
{
    extern __shared__ float sm[];
    float* w1  = sm;
    float* w2  = sm + 25000;
    float* b1  = sm + 30000;
    float* fs  = sm + 30500;
    float* hid = sm + 32100;
    int tid = threadIdx.x;
    int b0 = blockIdx.x * S3_G;

    for (int i = tid; i < 25000; i += 256) w1[i] = l1w[i];
    for (int i = tid; i < 5000;  i += 256) w2[i] = l2w[i];
    for (int i = tid; i < 500;   i += 256) b1[i] = l1b[i];
    for (int i = tid; i < S3_G * 50; i += 256) fs[i] = f3[b0 * 50 + i];
    __syncthreads();

    for (int hh = tid; hh < S3_G * 500; hh += 256) {
        int s = hh / 500, j = hh - s * 500;
        float a = b1[j];
        const float* fr = fs + s * 50;
        const float* wr = w1 + j * 50;
        #pragma unroll 10
        for (int k = 0; k < 50; k++) a += fr[k] * wr[k];
        hid[hh] = fmaxf(a, 0.f);
    }
    __syncthreads();

    for (int oo = tid; oo < S3_G * 10; oo += 256) {
        int s = oo / 10, n = oo - s * 10;
        float a = __ldg(&l2b[n]);
        const float* hr = hid + s * 500;
        const float* wr = w2 + n * 500;
        #pragma unroll 4
        for (int j = 0; j < 500; j++) a += hr[j] * wr[j];
        o3[(b0 + s) * 10 + n] = a;
    }
}

// ---------------- select + log_softmax -------------------------------------
__global__ void final_kernel(const int* __restrict__ e1, const int* __restrict__ e2,
                             const float* __restrict__ o1, const float* __restrict__ o2,
                             const float* __restrict__ o3, float* __restrict__ out)
{
    int b = blockIdx.x * blockDim.x + threadIdx.x;
    if (b >= BATCH) return;
    const float* s = e1[b] ? (o1 + b * 10) : (e2[b] ? (o2 + b * 10) : (o3 + b * 10));
    float v[10], mx = -1e30f;
    #pragma unroll
    for (int i = 0; i < 10; i++) { v[i] = s[i]; mx = fmaxf(mx, v[i]); }
    float sum = 0.f;
    #pragma unroll
    for (int i = 0; i < 10; i++) sum += expf(v[i] - mx);
    float l = logf(sum);
    #pragma unroll
    for (int i = 0; i < 10; i++) out[b * 10 + i] = v[i] - mx - l;
}

// ---------------- launch ----------------------------------------------------
extern "C" void kernel_launch(void* const* d_in, const int* in_sizes, int n_in,
                              void* d_out, int out_size)
{
    const float* x      = (const float*)d_in[0];
    const float* c1_w   = (const float*)d_in[1];
    const float* c1_b   = (const float*)d_in[2];
    const float* c2_w   = (const float*)d_in[3];
    const float* c2_b   = (const float*)d_in[4];
    const float* c3_w   = (const float*)d_in[5];
    const float* c3_b   = (const float*)d_in[6];
    const float* l1c1_w = (const float*)d_in[7];
    const float* l1c1_b = (const float*)d_in[8];
    const float* l2c1_w = (const float*)d_in[9];
    const float* l2c1_b = (const float*)d_in[10];
    const float* l1c2_w = (const float*)d_in[11];
    const float* l1c2_b = (const float*)d_in[12];
    const float* l2c2_w = (const float*)d_in[13];
    const float* l2c2_b = (const float*)d_in[14];
    const float* l1_w   = (const float*)d_in[15];
    const float* l1_b   = (const float*)d_in[16];
    const float* l2_w   = (const float*)d_in[17];
    const float* l2_b   = (const float*)d_in[18];
    const float* d1_w   = (const float*)d_in[19];
    const float* d1_b   = (const float*)d_in[20];
    const float* d2_w   = (const float*)d_in[21];
    const float* d2_b   = (const float*)d_in[22];
    float* out = (float*)d_out;

    float *h1, *h2, *f3, *o1, *o2, *o3, *W1, *W2, *b1c, *b2c;
    float2 *wpk1, *wpk2;
    int *e1, *e2;
    cudaGetSymbolAddress((void**)&h1,  g_h1);
    cudaGetSymbolAddress((void**)&h2,  g_h2);
    cudaGetSymbolAddress((void**)&f3,  g_f3);
    cudaGetSymbolAddress((void**)&o1,  g_o1);
    cudaGetSymbolAddress((void**)&o2,  g_o2);
    cudaGetSymbolAddress((void**)&o3,  g_o3);
    cudaGetSymbolAddress((void**)&e1,  g_e1);
    cudaGetSymbolAddress((void**)&e2,  g_e2);
    cudaGetSymbolAddress((void**)&W1,  g_W1);
    cudaGetSymbolAddress((void**)&W2,  g_W2);
    cudaGetSymbolAddress((void**)&b1c, g_b1c);
    cudaGetSymbolAddress((void**)&b2c, g_b2c);
    cudaGetSymbolAddress((void**)&wpk1, g_wpk1);
    cudaGetSymbolAddress((void**)&wpk2, g_wpk2);

    static int attr_set = 0;
    if (!attr_set) {
        cudaFuncSetAttribute(stagehead_kernel,
                             cudaFuncAttributeMaxDynamicSharedMemorySize, SH_SMEM);
        cudaFuncSetAttribute(stage3_kernel,
                             cudaFuncAttributeMaxDynamicSharedMemorySize, S3_SMEM);
        attr_set = 1;
    }

    // prep
    combine_kernel<<<(KP1P + 255) / 256, 256>>>(l1c1_w, l1c1_b, l2c1_w, l2c1_b,
                                                d1_w, d1_b, K1, KP1P, W1, b1c);
    combine_kernel<<<(KP2P + 255) / 256, 256>>>(l1c2_w, l1c2_b, l2c2_w, l2c2_b,
                                                d2_w, d2_b, K2, KP2P, W2, b2c);
    pack_w1_kernel<<<2, 256>>>(c1_w, wpk1);
    pack_w2_kernel<<<(50 * 450 + 255) / 256, 256>>>(c2_w, wpk2);

    // stage 1
    conv1_kernel<<<BATCH, 192>>>(x, wpk1, c1_b, h1);
    stagehead_kernel<<<BATCH / SH_G, 256, SH_SMEM>>>(h1, KP1P, W1, b1c, o1, e1);

    // stage 2
    conv2_kernel<<<BATCH, 256>>>(h1, wpk2, c2_b, h2, e1);
    stagehead_kernel<<<BATCH / SH_G, 256, SH_SMEM>>>(h2, KP2P, W2, b2c, o2, e2);

    // stage 3
    conv3_kernel<<<BATCH, 64>>>(h2, c3_w, c3_b, f3, e1, e2);
    stage3_kernel<<<BATCH / S3_G, 256, S3_SMEM>>>(f3, l1_w, l1_b, l2_w, l2_b, o3);

    final_kernel<<<(BATCH + 255) / 256, 256>>>(e1, e2, o1, o2, o3, out);
}